// round 1
// baseline (speedup 1.0000x reference)
#include <cuda_runtime.h>
#include <math.h>

#define BATCH 32
#define NSEQ  512
#define EMB   128
#define NHEAD 8
#define HDIM  16

// ---------------- scratch (no allocations allowed) ----------------
__device__ float g_K [BATCH*NSEQ*EMB];
__device__ float g_V [BATCH*NSEQ*EMB];
__device__ float g_Ke[BATCH*NSEQ*EMB];
__device__ float g_Ve[BATCH*NSEQ*EMB];
__device__ float g_Q [BATCH*NSEQ*EMB];
__device__ float g_O1[BATCH*NSEQ*EMB];
__device__ float g_O2[BATCH*NSEQ*EMB];
__device__ float g_MH[BATCH*NSEQ*EMB];

__device__ __forceinline__ float dot4(float4 a, float4 b) {
    return fmaf(a.x, b.x, fmaf(a.y, b.y, fmaf(a.z, b.z, a.w * b.w)));
}
__device__ __forceinline__ void fma4(float4& o, float p, float4 v) {
    o.x = fmaf(p, v.x, o.x); o.y = fmaf(p, v.y, o.y);
    o.z = fmaf(p, v.z, o.z); o.w = fmaf(p, v.w, o.w);
}
__device__ __forceinline__ void scale4(float4& o, float f) {
    o.x *= f; o.y *= f; o.z *= f; o.w *= f;
}

// ---------------- projection GEMM: Out = X @ W  (M=16384, N=K=128) ----------------
// block: 256 threads, 64 rows. which selects target scratch buffer.
__global__ void proj_kernel(const float* __restrict__ X, const float* __restrict__ W, int which) {
    __shared__ float sW[32 * 128];
    __shared__ float sA[64 * 33];
    float* Out = (which == 0) ? g_K : (which == 1) ? g_V : (which == 2) ? g_Ke : g_Ve;

    int t = threadIdx.x;
    int lane = t & 31, w = t >> 5;
    int row0 = blockIdx.x * 64;
    float acc[8][4];
#pragma unroll
    for (int i = 0; i < 8; i++) { acc[i][0]=0.f; acc[i][1]=0.f; acc[i][2]=0.f; acc[i][3]=0.f; }

    for (int k0 = 0; k0 < 128; k0 += 32) {
        __syncthreads();
        for (int i = t; i < 32 * 128; i += 256)
            sW[i] = W[(k0 + (i >> 7)) * 128 + (i & 127)];
        for (int i = t; i < 64 * 32; i += 256) {
            int r = i >> 5, kk = i & 31;
            sA[r * 33 + kk] = X[(row0 + r) * 128 + k0 + kk];
        }
        __syncthreads();
#pragma unroll 8
        for (int kk = 0; kk < 32; kk++) {
            float wv0 = sW[kk * 128 + lane];
            float wv1 = sW[kk * 128 + lane + 32];
            float wv2 = sW[kk * 128 + lane + 64];
            float wv3 = sW[kk * 128 + lane + 96];
#pragma unroll
            for (int i = 0; i < 8; i++) {
                float a = sA[(w * 8 + i) * 33 + kk];
                acc[i][0] = fmaf(a, wv0, acc[i][0]);
                acc[i][1] = fmaf(a, wv1, acc[i][1]);
                acc[i][2] = fmaf(a, wv2, acc[i][2]);
                acc[i][3] = fmaf(a, wv3, acc[i][3]);
            }
        }
    }
#pragma unroll
    for (int i = 0; i < 8; i++) {
        int r = row0 + w * 8 + i;
        Out[r * 128 + lane]      = acc[i][0];
        Out[r * 128 + lane + 32] = acc[i][1];
        Out[r * 128 + lane + 64] = acc[i][2];
        Out[r * 128 + lane + 96] = acc[i][3];
    }
}

// ---------------- fused Q projection: g_Q = sum_{p=0..3} Xp @ Wp ----------------
__global__ void qproj_kernel(const float* __restrict__ X0, const float* __restrict__ W0,
                             const float* __restrict__ X1, const float* __restrict__ W1,
                             const float* __restrict__ X2, const float* __restrict__ W2,
                             const float* __restrict__ X3, const float* __restrict__ W3) {
    __shared__ float sW[32 * 128];
    __shared__ float sA[64 * 33];
    int t = threadIdx.x;
    int lane = t & 31, w = t >> 5;
    int row0 = blockIdx.x * 64;
    float acc[8][4];
#pragma unroll
    for (int i = 0; i < 8; i++) { acc[i][0]=0.f; acc[i][1]=0.f; acc[i][2]=0.f; acc[i][3]=0.f; }

    const float* Xs[4] = {X0, X1, X2, X3};
    const float* Ws[4] = {W0, W1, W2, W3};

    for (int p = 0; p < 4; p++) {
        const float* X = Xs[p];
        const float* W = Ws[p];
        for (int k0 = 0; k0 < 128; k0 += 32) {
            __syncthreads();
            for (int i = t; i < 32 * 128; i += 256)
                sW[i] = W[(k0 + (i >> 7)) * 128 + (i & 127)];
            for (int i = t; i < 64 * 32; i += 256) {
                int r = i >> 5, kk = i & 31;
                sA[r * 33 + kk] = X[(row0 + r) * 128 + k0 + kk];
            }
            __syncthreads();
#pragma unroll 8
            for (int kk = 0; kk < 32; kk++) {
                float wv0 = sW[kk * 128 + lane];
                float wv1 = sW[kk * 128 + lane + 32];
                float wv2 = sW[kk * 128 + lane + 64];
                float wv3 = sW[kk * 128 + lane + 96];
#pragma unroll
                for (int i = 0; i < 8; i++) {
                    float a = sA[(w * 8 + i) * 33 + kk];
                    acc[i][0] = fmaf(a, wv0, acc[i][0]);
                    acc[i][1] = fmaf(a, wv1, acc[i][1]);
                    acc[i][2] = fmaf(a, wv2, acc[i][2]);
                    acc[i][3] = fmaf(a, wv3, acc[i][3]);
                }
            }
        }
    }
#pragma unroll
    for (int i = 0; i < 8; i++) {
        int r = row0 + w * 8 + i;
        g_Q[r * 128 + lane]      = acc[i][0];
        g_Q[r * 128 + lane + 32] = acc[i][1];
        g_Q[r * 128 + lane + 64] = acc[i][2];
        g_Q[r * 128 + lane + 96] = acc[i][3];
    }
}

// ---------------- combine: g_MH = g_O1 @ W1 + b1 + g_O2 @ W2 + b2 ----------------
__global__ void comb_kernel(const float* __restrict__ W1, const float* __restrict__ b1,
                            const float* __restrict__ W2, const float* __restrict__ b2) {
    __shared__ float sW[32 * 128];
    __shared__ float sA[64 * 33];
    int t = threadIdx.x;
    int lane = t & 31, w = t >> 5;
    int row0 = blockIdx.x * 64;
    float acc[8][4];
#pragma unroll
    for (int i = 0; i < 8; i++) { acc[i][0]=0.f; acc[i][1]=0.f; acc[i][2]=0.f; acc[i][3]=0.f; }

    const float* Xs[2] = {g_O1, g_O2};
    const float* Ws[2] = {W1, W2};

    for (int p = 0; p < 2; p++) {
        const float* X = Xs[p];
        const float* W = Ws[p];
        for (int k0 = 0; k0 < 128; k0 += 32) {
            __syncthreads();
            for (int i = t; i < 32 * 128; i += 256)
                sW[i] = W[(k0 + (i >> 7)) * 128 + (i & 127)];
            for (int i = t; i < 64 * 32; i += 256) {
                int r = i >> 5, kk = i & 31;
                sA[r * 33 + kk] = X[(row0 + r) * 128 + k0 + kk];
            }
            __syncthreads();
#pragma unroll 8
            for (int kk = 0; kk < 32; kk++) {
                float wv0 = sW[kk * 128 + lane];
                float wv1 = sW[kk * 128 + lane + 32];
                float wv2 = sW[kk * 128 + lane + 64];
                float wv3 = sW[kk * 128 + lane + 96];
#pragma unroll
                for (int i = 0; i < 8; i++) {
                    float a = sA[(w * 8 + i) * 33 + kk];
                    acc[i][0] = fmaf(a, wv0, acc[i][0]);
                    acc[i][1] = fmaf(a, wv1, acc[i][1]);
                    acc[i][2] = fmaf(a, wv2, acc[i][2]);
                    acc[i][3] = fmaf(a, wv3, acc[i][3]);
                }
            }
        }
    }
    float bias0 = b1[lane]      + b2[lane];
    float bias1 = b1[lane + 32] + b2[lane + 32];
    float bias2 = b1[lane + 64] + b2[lane + 64];
    float bias3 = b1[lane + 96] + b2[lane + 96];
#pragma unroll
    for (int i = 0; i < 8; i++) {
        int r = row0 + w * 8 + i;
        g_MH[r * 128 + lane]      = acc[i][0] + bias0;
        g_MH[r * 128 + lane + 32] = acc[i][1] + bias1;
        g_MH[r * 128 + lane + 64] = acc[i][2] + bias2;
        g_MH[r * 128 + lane + 96] = acc[i][3] + bias3;
    }
}

// ---------------- dual flash attention ----------------
// grid (4 row-tiles, NHEAD, BATCH), block 128 threads (1 row per thread).
__global__ void attn_kernel(const float* __restrict__ mask) {
    __shared__ float4 sK [32][4];
    __shared__ float4 sV [32][4];
    __shared__ float4 sKe[32][4];
    __shared__ float4 sVe[32][4];
    __shared__ float  sM[128 * 33];

    int t = threadIdx.x;
    int lane = t & 31, w = t >> 5;
    int b = blockIdx.z, h = blockIdx.y;
    int row = blockIdx.x * 128 + t;

    const float4* qp = reinterpret_cast<const float4*>(g_Q + ((b * NSEQ + row) * EMB + h * HDIM));
    float4 q0 = qp[0], q1 = qp[1], q2 = qp[2], q3 = qp[3];

    float m1 = -1e30f, l1 = 0.f;
    float m2 = -1e30f, l2 = 0.f;
    float4 o1a = {0,0,0,0}, o1b = {0,0,0,0}, o1c = {0,0,0,0}, o1d = {0,0,0,0};
    float4 o2a = {0,0,0,0}, o2b = {0,0,0,0}, o2c = {0,0,0,0}, o2d = {0,0,0,0};

    int key = t >> 2, part = t & 3;

    for (int c0 = 0; c0 < NSEQ; c0 += 32) {
        __syncthreads();
        // stage K/V/Ke/Ve tiles (fully coalesced 64B per key)
        {
            int gbase = (b * NSEQ + c0 + key) * EMB + h * HDIM + part * 4;
            sK [key][part] = *reinterpret_cast<const float4*>(g_K  + gbase);
            sV [key][part] = *reinterpret_cast<const float4*>(g_V  + gbase);
            sKe[key][part] = *reinterpret_cast<const float4*>(g_Ke + gbase);
            sVe[key][part] = *reinterpret_cast<const float4*>(g_Ve + gbase);
        }
        // stage mask tile coalesced: warp w covers rows w, w+4, ...
        {
            int rbase = (b * NSEQ + blockIdx.x * 128) * NSEQ + c0 + lane;
#pragma unroll 8
            for (int ii = 0; ii < 32; ii++) {
                int rr = w + ii * 4;
                sM[rr * 33 + lane] = mask[rbase + rr * NSEQ];
            }
        }
        __syncthreads();

#pragma unroll 4
        for (int k = 0; k < 32; k++) {
            float mval = sM[t * 33 + k];
            // attention 1
            {
                float s = dot4(q0, sK[k][0]) + dot4(q1, sK[k][1])
                        + dot4(q2, sK[k][2]) + dot4(q3, sK[k][3]);
                s = fmaf(s, 0.25f, mval);
                if (s > m1) {
                    float f = __expf(m1 - s);
                    l1 *= f; scale4(o1a, f); scale4(o1b, f); scale4(o1c, f); scale4(o1d, f);
                    m1 = s;
                }
                float p = __expf(s - m1);
                l1 += p;
                fma4(o1a, p, sV[k][0]); fma4(o1b, p, sV[k][1]);
                fma4(o1c, p, sV[k][2]); fma4(o1d, p, sV[k][3]);
            }
            // attention 2
            {
                float s = dot4(q0, sKe[k][0]) + dot4(q1, sKe[k][1])
                        + dot4(q2, sKe[k][2]) + dot4(q3, sKe[k][3]);
                s = fmaf(s, 0.25f, mval);
                if (s > m2) {
                    float f = __expf(m2 - s);
                    l2 *= f; scale4(o2a, f); scale4(o2b, f); scale4(o2c, f); scale4(o2d, f);
                    m2 = s;
                }
                float p = __expf(s - m2);
                l2 += p;
                fma4(o2a, p, sVe[k][0]); fma4(o2b, p, sVe[k][1]);
                fma4(o2c, p, sVe[k][2]); fma4(o2d, p, sVe[k][3]);
            }
        }
    }

    float inv1 = 1.f / l1, inv2 = 1.f / l2;
    scale4(o1a, inv1); scale4(o1b, inv1); scale4(o1c, inv1); scale4(o1d, inv1);
    scale4(o2a, inv2); scale4(o2b, inv2); scale4(o2c, inv2); scale4(o2d, inv2);

    float4* p1 = reinterpret_cast<float4*>(g_O1 + ((b * NSEQ + row) * EMB + h * HDIM));
    float4* p2 = reinterpret_cast<float4*>(g_O2 + ((b * NSEQ + row) * EMB + h * HDIM));
    p1[0] = o1a; p1[1] = o1b; p1[2] = o1c; p1[3] = o1d;
    p2[0] = o2a; p2[1] = o2b; p2[2] = o2c; p2[3] = o2d;
}

// ---------------- final score: logits = 10*tanh((g_MH @ shk^T)/sqrt(128)) + mask ----------------
// shk = nodes + graph computed on the fly. grid (8,8,BATCH), block 256 (16x16, 4x4 microtile).
__global__ void score_kernel(const float* __restrict__ nodes, const float* __restrict__ graph,
                             const float* __restrict__ mask, float* __restrict__ out) {
    __shared__ float sA[64 * 65];
    __shared__ float sB[64 * 65];
    int t = threadIdx.x;
    int b = blockIdx.z;
    int c0 = blockIdx.x * 64, r0 = blockIdx.y * 64;
    int tyi = t >> 4, txi = t & 15;

    float acc[4][4];
#pragma unroll
    for (int i = 0; i < 4; i++)
#pragma unroll
        for (int j = 0; j < 4; j++) acc[i][j] = 0.f;

    for (int k0 = 0; k0 < 128; k0 += 64) {
        __syncthreads();
        for (int i = t; i < 64 * 64; i += 256) {
            int r = i >> 6, kk = i & 63;
            sA[r * 65 + kk] = g_MH[(b * NSEQ + r0 + r) * EMB + k0 + kk];
            int gi = (b * NSEQ + c0 + r) * EMB + k0 + kk;
            sB[r * 65 + kk] = nodes[gi] + graph[gi];
        }
        __syncthreads();
#pragma unroll 8
        for (int kk = 0; kk < 64; kk++) {
            float a[4], bb[4];
#pragma unroll
            for (int i = 0; i < 4; i++) a[i]  = sA[(tyi * 4 + i) * 65 + kk];
#pragma unroll
            for (int j = 0; j < 4; j++) bb[j] = sB[(txi * 4 + j) * 65 + kk];
#pragma unroll
            for (int i = 0; i < 4; i++)
#pragma unroll
                for (int j = 0; j < 4; j++)
                    acc[i][j] = fmaf(a[i], bb[j], acc[i][j]);
        }
    }

    const float inv_sqrt_emb = 0.08838834764831845f;  // 1/sqrt(128)
#pragma unroll
    for (int i = 0; i < 4; i++) {
        int r = r0 + tyi * 4 + i;
#pragma unroll
        for (int j = 0; j < 4; j++) {
            int c = c0 + txi * 4 + j;
            int gi = (b * NSEQ + r) * NSEQ + c;
            out[gi] = fmaf(10.f, tanhf(acc[i][j] * inv_sqrt_emb), mask[gi]);
        }
    }
}

// ---------------- in-place row softmax over d_out ----------------
__global__ void softmax_kernel(float* __restrict__ out) {
    float* p = out + (size_t)blockIdx.x * NSEQ;
    int t = threadIdx.x;  // 128 threads
    float v[4];
    float mx = -1e30f;
#pragma unroll
    for (int i = 0; i < 4; i++) { v[i] = p[t + i * 128]; mx = fmaxf(mx, v[i]); }
#pragma unroll
    for (int o = 16; o; o >>= 1) mx = fmaxf(mx, __shfl_xor_sync(0xffffffffu, mx, o));
    __shared__ float sm[4];
    if ((t & 31) == 0) sm[t >> 5] = mx;
    __syncthreads();
    mx = fmaxf(fmaxf(sm[0], sm[1]), fmaxf(sm[2], sm[3]));

    float sum = 0.f;
#pragma unroll
    for (int i = 0; i < 4; i++) { v[i] = __expf(v[i] - mx); sum += v[i]; }
#pragma unroll
    for (int o = 16; o; o >>= 1) sum += __shfl_xor_sync(0xffffffffu, sum, o);
    __shared__ float ss[4];
    if ((t & 31) == 0) ss[t >> 5] = sum;
    __syncthreads();
    sum = ss[0] + ss[1] + ss[2] + ss[3];

    float inv = 1.f / sum;
#pragma unroll
    for (int i = 0; i < 4; i++) p[t + i * 128] = v[i] * inv;
}

// ---------------- launch ----------------
extern "C" void kernel_launch(void* const* d_in, const int* in_sizes, int n_in,
                              void* d_out, int out_size) {
    const float* enc_nodes = (const float*)d_in[0];
    const float* enc_graph = (const float*)d_in[1];
    const float* enc_q1    = (const float*)d_in[2];
    const float* enc_fg    = (const float*)d_in[3];
    const float* enc_ln    = (const float*)d_in[4];
    const float* enc_lg    = (const float*)d_in[5];
    const float* mask      = (const float*)d_in[6];
    const float* Wq_first  = (const float*)d_in[7];
    const float* Wq_last   = (const float*)d_in[8];
    const float* Wk        = (const float*)d_in[9];
    const float* Wv        = (const float*)d_in[10];
    const float* Wq_first_e= (const float*)d_in[11];
    const float* Wq_last_e = (const float*)d_in[12];
    const float* Wk_e      = (const float*)d_in[13];
    const float* Wv_e      = (const float*)d_in[14];
    const float* Wcomb1    = (const float*)d_in[15];
    const float* bcomb1    = (const float*)d_in[16];
    const float* Wcomb2    = (const float*)d_in[17];
    const float* bcomb2    = (const float*)d_in[18];
    float* out = (float*)d_out;

    const int M_BLOCKS = (BATCH * NSEQ) / 64;  // 256

    proj_kernel<<<M_BLOCKS, 256>>>(enc_nodes, Wk,   0);
    proj_kernel<<<M_BLOCKS, 256>>>(enc_nodes, Wv,   1);
    proj_kernel<<<M_BLOCKS, 256>>>(enc_graph, Wk_e, 2);
    proj_kernel<<<M_BLOCKS, 256>>>(enc_graph, Wv_e, 3);
    qproj_kernel<<<M_BLOCKS, 256>>>(enc_q1, Wq_first, enc_ln, Wq_last,
                                    enc_fg, Wq_first_e, enc_lg, Wq_last_e);
    attn_kernel<<<dim3(4, NHEAD, BATCH), 128>>>(mask);
    comb_kernel<<<M_BLOCKS, 256>>>(Wcomb1, bcomb1, Wcomb2, bcomb2);
    score_kernel<<<dim3(8, 8, BATCH), 256>>>(enc_nodes, enc_graph, mask, out);
    softmax_kernel<<<BATCH * NSEQ, 128>>>(out);
}

// round 2
// speedup vs baseline: 1.2043x; 1.2043x over previous
#include <cuda_runtime.h>
#include <math.h>

#define BATCH 32
#define NSEQ  512
#define EMB   128
#define NHEAD 8
#define HDIM  16

// ---------------- scratch (no allocations allowed) ----------------
__device__ float g_K [BATCH*NSEQ*EMB];
__device__ float g_V [BATCH*NSEQ*EMB];
__device__ float g_Ke[BATCH*NSEQ*EMB];
__device__ float g_Ve[BATCH*NSEQ*EMB];
__device__ float g_Q [BATCH*NSEQ*EMB];
__device__ float g_O1[BATCH*NSEQ*EMB];
__device__ float g_O2[BATCH*NSEQ*EMB];
__device__ float g_MH[BATCH*NSEQ*EMB];

__device__ __forceinline__ float dot4(float4 a, float4 b) {
    return fmaf(a.x, b.x, fmaf(a.y, b.y, fmaf(a.z, b.z, a.w * b.w)));
}
__device__ __forceinline__ void fma4(float4& o, float p, float4 v) {
    o.x = fmaf(p, v.x, o.x); o.y = fmaf(p, v.y, o.y);
    o.z = fmaf(p, v.z, o.z); o.w = fmaf(p, v.w, o.w);
}
__device__ __forceinline__ void scale4(float4& o, float f) {
    o.x *= f; o.y *= f; o.z *= f; o.w *= f;
}
__device__ __forceinline__ float fast_tanh(float x) {
    float e = __expf(2.f * x);
    return 1.f - __fdividef(2.f, e + 1.f);
}

// ======================================================================
// proj4: K/V/Ke/Ve projections. 128x128 tile, 8x8 microtile, BK=16.
// grid (128, 4), block 256.
// ======================================================================
__global__ void __launch_bounds__(256) proj4_kernel(
        const float* __restrict__ nodes, const float* __restrict__ graph,
        const float* __restrict__ Wk, const float* __restrict__ Wv,
        const float* __restrict__ Wke, const float* __restrict__ Wve) {
    __shared__ float sAT[16 * 132];
    __shared__ float sB [16 * 128];
    int z = blockIdx.y;
    const float* X = (z < 2) ? nodes : graph;
    const float* W = (z == 0) ? Wk : (z == 1) ? Wv : (z == 2) ? Wke : Wve;
    float* Out = (z == 0) ? g_K : (z == 1) ? g_V : (z == 2) ? g_Ke : g_Ve;

    int t = threadIdx.x;
    int tx = t & 15, ty = t >> 4;
    int row0 = blockIdx.x * 128;

    float acc[8][8];
#pragma unroll
    for (int i = 0; i < 8; i++)
#pragma unroll
        for (int j = 0; j < 8; j++) acc[i][j] = 0.f;

    for (int k0 = 0; k0 < 128; k0 += 16) {
        __syncthreads();
#pragma unroll
        for (int j = 0; j < 2; j++) {
            int idx = t + j * 256;
            int row = idx >> 2, k4 = (idx & 3) * 4;
            float4 v = *reinterpret_cast<const float4*>(&X[(row0 + row) * 128 + k0 + k4]);
            sAT[(k4 + 0) * 132 + row] = v.x;
            sAT[(k4 + 1) * 132 + row] = v.y;
            sAT[(k4 + 2) * 132 + row] = v.z;
            sAT[(k4 + 3) * 132 + row] = v.w;
        }
#pragma unroll
        for (int j = 0; j < 2; j++) {
            int idx = t + j * 256;
            int kk = idx >> 5, c4 = (idx & 31) * 4;
            *reinterpret_cast<float4*>(&sB[kk * 128 + c4]) =
                *reinterpret_cast<const float4*>(&W[(k0 + kk) * 128 + c4]);
        }
        __syncthreads();
#pragma unroll
        for (int kk = 0; kk < 16; kk++) {
            float4 a0 = *reinterpret_cast<float4*>(&sAT[kk * 132 + ty * 8]);
            float4 a1 = *reinterpret_cast<float4*>(&sAT[kk * 132 + ty * 8 + 4]);
            float4 b0 = *reinterpret_cast<float4*>(&sB [kk * 128 + tx * 8]);
            float4 b1 = *reinterpret_cast<float4*>(&sB [kk * 128 + tx * 8 + 4]);
            float a[8] = {a0.x,a0.y,a0.z,a0.w,a1.x,a1.y,a1.z,a1.w};
            float b[8] = {b0.x,b0.y,b0.z,b0.w,b1.x,b1.y,b1.z,b1.w};
#pragma unroll
            for (int i = 0; i < 8; i++)
#pragma unroll
                for (int j = 0; j < 8; j++)
                    acc[i][j] = fmaf(a[i], b[j], acc[i][j]);
        }
    }
#pragma unroll
    for (int i = 0; i < 8; i++) {
        int r = row0 + ty * 8 + i;
        *reinterpret_cast<float4*>(&Out[r * 128 + tx * 8]) =
            make_float4(acc[i][0], acc[i][1], acc[i][2], acc[i][3]);
        *reinterpret_cast<float4*>(&Out[r * 128 + tx * 8 + 4]) =
            make_float4(acc[i][4], acc[i][5], acc[i][6], acc[i][7]);
    }
}

// ======================================================================
// qproj: g_Q = sum_{p} Xp @ Wp.  64x128 tile, 4x8 micro, BK=16.
// grid (256), block 256.
// ======================================================================
__global__ void __launch_bounds__(256) qproj_kernel(
        const float* __restrict__ X0, const float* __restrict__ W0,
        const float* __restrict__ X1, const float* __restrict__ W1,
        const float* __restrict__ X2, const float* __restrict__ W2,
        const float* __restrict__ X3, const float* __restrict__ W3) {
    __shared__ float sAT[16 * 68];
    __shared__ float sB [16 * 128];
    int t = threadIdx.x;
    int tx = t & 15, ty = t >> 4;
    int row0 = blockIdx.x * 64;

    float acc[4][8];
#pragma unroll
    for (int i = 0; i < 4; i++)
#pragma unroll
        for (int j = 0; j < 8; j++) acc[i][j] = 0.f;

    const float* Xs[4] = {X0, X1, X2, X3};
    const float* Ws[4] = {W0, W1, W2, W3};

    for (int p = 0; p < 4; p++) {
        const float* X = Xs[p];
        const float* W = Ws[p];
        for (int k0 = 0; k0 < 128; k0 += 16) {
            __syncthreads();
            {
                int row = t >> 2, k4 = (t & 3) * 4;
                float4 v = *reinterpret_cast<const float4*>(&X[(row0 + row) * 128 + k0 + k4]);
                sAT[(k4 + 0) * 68 + row] = v.x;
                sAT[(k4 + 1) * 68 + row] = v.y;
                sAT[(k4 + 2) * 68 + row] = v.z;
                sAT[(k4 + 3) * 68 + row] = v.w;
            }
#pragma unroll
            for (int j = 0; j < 2; j++) {
                int idx = t + j * 256;
                int kk = idx >> 5, c4 = (idx & 31) * 4;
                *reinterpret_cast<float4*>(&sB[kk * 128 + c4]) =
                    *reinterpret_cast<const float4*>(&W[(k0 + kk) * 128 + c4]);
            }
            __syncthreads();
#pragma unroll
            for (int kk = 0; kk < 16; kk++) {
                float4 a0 = *reinterpret_cast<float4*>(&sAT[kk * 68 + ty * 4]);
                float4 b0 = *reinterpret_cast<float4*>(&sB [kk * 128 + tx * 8]);
                float4 b1 = *reinterpret_cast<float4*>(&sB [kk * 128 + tx * 8 + 4]);
                float a[4] = {a0.x,a0.y,a0.z,a0.w};
                float b[8] = {b0.x,b0.y,b0.z,b0.w,b1.x,b1.y,b1.z,b1.w};
#pragma unroll
                for (int i = 0; i < 4; i++)
#pragma unroll
                    for (int j = 0; j < 8; j++)
                        acc[i][j] = fmaf(a[i], b[j], acc[i][j]);
            }
        }
    }
#pragma unroll
    for (int i = 0; i < 4; i++) {
        int r = row0 + ty * 4 + i;
        *reinterpret_cast<float4*>(&g_Q[r * 128 + tx * 8]) =
            make_float4(acc[i][0], acc[i][1], acc[i][2], acc[i][3]);
        *reinterpret_cast<float4*>(&g_Q[r * 128 + tx * 8 + 4]) =
            make_float4(acc[i][4], acc[i][5], acc[i][6], acc[i][7]);
    }
}

// ======================================================================
// comb: g_MH = g_O1@W1 + b1 + g_O2@W2 + b2.  64x128 tile, 4x8 micro.
// grid (256), block 256.
// ======================================================================
__global__ void __launch_bounds__(256) comb_kernel(
        const float* __restrict__ W1, const float* __restrict__ b1,
        const float* __restrict__ W2, const float* __restrict__ b2) {
    __shared__ float sAT[16 * 68];
    __shared__ float sB [16 * 128];
    int t = threadIdx.x;
    int tx = t & 15, ty = t >> 4;
    int row0 = blockIdx.x * 64;

    float acc[4][8];
#pragma unroll
    for (int i = 0; i < 4; i++)
#pragma unroll
        for (int j = 0; j < 8; j++) acc[i][j] = 0.f;

    const float* Xs[2] = {g_O1, g_O2};
    const float* Ws[2] = {W1, W2};

    for (int p = 0; p < 2; p++) {
        const float* X = Xs[p];
        const float* W = Ws[p];
        for (int k0 = 0; k0 < 128; k0 += 16) {
            __syncthreads();
            {
                int row = t >> 2, k4 = (t & 3) * 4;
                float4 v = *reinterpret_cast<const float4*>(&X[(row0 + row) * 128 + k0 + k4]);
                sAT[(k4 + 0) * 68 + row] = v.x;
                sAT[(k4 + 1) * 68 + row] = v.y;
                sAT[(k4 + 2) * 68 + row] = v.z;
                sAT[(k4 + 3) * 68 + row] = v.w;
            }
#pragma unroll
            for (int j = 0; j < 2; j++) {
                int idx = t + j * 256;
                int kk = idx >> 5, c4 = (idx & 31) * 4;
                *reinterpret_cast<float4*>(&sB[kk * 128 + c4]) =
                    *reinterpret_cast<const float4*>(&W[(k0 + kk) * 128 + c4]);
            }
            __syncthreads();
#pragma unroll
            for (int kk = 0; kk < 16; kk++) {
                float4 a0 = *reinterpret_cast<float4*>(&sAT[kk * 68 + ty * 4]);
                float4 b0 = *reinterpret_cast<float4*>(&sB [kk * 128 + tx * 8]);
                float4 b1 = *reinterpret_cast<float4*>(&sB [kk * 128 + tx * 8 + 4]);
                float a[4] = {a0.x,a0.y,a0.z,a0.w};
                float b[8] = {b0.x,b0.y,b0.z,b0.w,b1.x,b1.y,b1.z,b1.w};
#pragma unroll
                for (int i = 0; i < 4; i++)
#pragma unroll
                    for (int j = 0; j < 8; j++)
                        acc[i][j] = fmaf(a[i], b[j], acc[i][j]);
            }
        }
    }
    float bias[8];
#pragma unroll
    for (int j = 0; j < 8; j++) bias[j] = b1[tx * 8 + j] + b2[tx * 8 + j];
#pragma unroll
    for (int i = 0; i < 4; i++) {
        int r = row0 + ty * 4 + i;
        *reinterpret_cast<float4*>(&g_MH[r * 128 + tx * 8]) =
            make_float4(acc[i][0]+bias[0], acc[i][1]+bias[1], acc[i][2]+bias[2], acc[i][3]+bias[3]);
        *reinterpret_cast<float4*>(&g_MH[r * 128 + tx * 8 + 4]) =
            make_float4(acc[i][4]+bias[4], acc[i][5]+bias[5], acc[i][6]+bias[6], acc[i][7]+bias[7]);
    }
}

// ======================================================================
// dual attention, branchless (no running max; scores are small, clamp 60).
// grid (2, NHEAD, BATCH), block 128; each thread handles 2 rows.
// ======================================================================
__global__ void attn_kernel(const float* __restrict__ mask) {
    __shared__ float4 sK [32][4];
    __shared__ float4 sV [32][4];
    __shared__ float4 sKe[32][4];
    __shared__ float4 sVe[32][4];
    __shared__ float  sM[256 * 33];

    int t = threadIdx.x;
    int b = blockIdx.z, h = blockIdx.y;
    int r0 = blockIdx.x * 256;
    int ra = r0 + t, rb = r0 + t + 128;

    const float4* qap = reinterpret_cast<const float4*>(g_Q + ((b * NSEQ + ra) * EMB + h * HDIM));
    const float4* qbp = reinterpret_cast<const float4*>(g_Q + ((b * NSEQ + rb) * EMB + h * HDIM));
    float4 qa0 = qap[0], qa1 = qap[1], qa2 = qap[2], qa3 = qap[3];
    float4 qb0 = qbp[0], qb1 = qbp[1], qb2 = qbp[2], qb3 = qbp[3];

    float la1 = 0.f, la2 = 0.f, lb1 = 0.f, lb2 = 0.f;
    float4 oa1[4] = {{0,0,0,0},{0,0,0,0},{0,0,0,0},{0,0,0,0}};
    float4 oa2[4] = {{0,0,0,0},{0,0,0,0},{0,0,0,0},{0,0,0,0}};
    float4 ob1[4] = {{0,0,0,0},{0,0,0,0},{0,0,0,0},{0,0,0,0}};
    float4 ob2[4] = {{0,0,0,0},{0,0,0,0},{0,0,0,0},{0,0,0,0}};

    int key = t >> 2, part = t & 3;

    for (int c0 = 0; c0 < NSEQ; c0 += 32) {
        __syncthreads();
        {
            int gb = (b * NSEQ + c0 + key) * EMB + h * HDIM + part * 4;
            sK [key][part] = *reinterpret_cast<const float4*>(g_K  + gb);
            sV [key][part] = *reinterpret_cast<const float4*>(g_V  + gb);
            sKe[key][part] = *reinterpret_cast<const float4*>(g_Ke + gb);
            sVe[key][part] = *reinterpret_cast<const float4*>(g_Ve + gb);
        }
#pragma unroll
        for (int j = 0; j < 16; j++) {
            int idx = t + j * 128;
            int row = idx >> 3, c4 = (idx & 7) * 4;
            float4 mv = *reinterpret_cast<const float4*>(
                &mask[(b * NSEQ + r0 + row) * NSEQ + c0 + c4]);
            sM[row * 33 + c4 + 0] = mv.x;
            sM[row * 33 + c4 + 1] = mv.y;
            sM[row * 33 + c4 + 2] = mv.z;
            sM[row * 33 + c4 + 3] = mv.w;
        }
        __syncthreads();

#pragma unroll 4
        for (int k = 0; k < 32; k++) {
            float ma = sM[t * 33 + k];
            float mb = sM[(t + 128) * 33 + k];
            // ----- attention 1 -----
            {
                float4 k0 = sK[k][0], k1 = sK[k][1], k2 = sK[k][2], k3 = sK[k][3];
                float sa = dot4(qa0,k0) + dot4(qa1,k1) + dot4(qa2,k2) + dot4(qa3,k3);
                float sb = dot4(qb0,k0) + dot4(qb1,k1) + dot4(qb2,k2) + dot4(qb3,k3);
                float pa = __expf(fminf(fmaf(sa, 0.25f, ma), 60.f));
                float pb = __expf(fminf(fmaf(sb, 0.25f, mb), 60.f));
                la1 += pa; lb1 += pb;
                float4 v0 = sV[k][0], v1 = sV[k][1], v2 = sV[k][2], v3 = sV[k][3];
                fma4(oa1[0], pa, v0); fma4(oa1[1], pa, v1);
                fma4(oa1[2], pa, v2); fma4(oa1[3], pa, v3);
                fma4(ob1[0], pb, v0); fma4(ob1[1], pb, v1);
                fma4(ob1[2], pb, v2); fma4(ob1[3], pb, v3);
            }
            // ----- attention 2 -----
            {
                float4 k0 = sKe[k][0], k1 = sKe[k][1], k2 = sKe[k][2], k3 = sKe[k][3];
                float sa = dot4(qa0,k0) + dot4(qa1,k1) + dot4(qa2,k2) + dot4(qa3,k3);
                float sb = dot4(qb0,k0) + dot4(qb1,k1) + dot4(qb2,k2) + dot4(qb3,k3);
                float pa = __expf(fminf(fmaf(sa, 0.25f, ma), 60.f));
                float pb = __expf(fminf(fmaf(sb, 0.25f, mb), 60.f));
                la2 += pa; lb2 += pb;
                float4 v0 = sVe[k][0], v1 = sVe[k][1], v2 = sVe[k][2], v3 = sVe[k][3];
                fma4(oa2[0], pa, v0); fma4(oa2[1], pa, v1);
                fma4(oa2[2], pa, v2); fma4(oa2[3], pa, v3);
                fma4(ob2[0], pb, v0); fma4(ob2[1], pb, v1);
                fma4(ob2[2], pb, v2); fma4(ob2[3], pb, v3);
            }
        }
    }

    float ia1 = 1.f / la1, ia2 = 1.f / la2, ib1 = 1.f / lb1, ib2 = 1.f / lb2;
#pragma unroll
    for (int i = 0; i < 4; i++) { scale4(oa1[i], ia1); scale4(oa2[i], ia2);
                                  scale4(ob1[i], ib1); scale4(ob2[i], ib2); }

    float4* pa1 = reinterpret_cast<float4*>(g_O1 + ((b * NSEQ + ra) * EMB + h * HDIM));
    float4* pa2 = reinterpret_cast<float4*>(g_O2 + ((b * NSEQ + ra) * EMB + h * HDIM));
    float4* pb1 = reinterpret_cast<float4*>(g_O1 + ((b * NSEQ + rb) * EMB + h * HDIM));
    float4* pb2 = reinterpret_cast<float4*>(g_O2 + ((b * NSEQ + rb) * EMB + h * HDIM));
#pragma unroll
    for (int i = 0; i < 4; i++) { pa1[i] = oa1[i]; pa2[i] = oa2[i];
                                  pb1[i] = ob1[i]; pb2[i] = ob2[i]; }
}

// ======================================================================
// score: logits = 10*tanh((g_MH @ shk^T)/sqrt(128)) + mask
// 128x128 tile, 8x8 micro, BK=16, both operands transposed-in-smem.
// grid (4, 4, BATCH), block 256.
// ======================================================================
__global__ void __launch_bounds__(256) score_kernel(
        const float* __restrict__ nodes, const float* __restrict__ graph,
        const float* __restrict__ mask, float* __restrict__ out) {
    __shared__ float sAT[16 * 132];
    __shared__ float sBT[16 * 132];
    int t = threadIdx.x;
    int tx = t & 15, ty = t >> 4;
    int b = blockIdx.z;
    int c0 = blockIdx.x * 128, r0 = blockIdx.y * 128;

    float acc[8][8];
#pragma unroll
    for (int i = 0; i < 8; i++)
#pragma unroll
        for (int j = 0; j < 8; j++) acc[i][j] = 0.f;

    for (int k0 = 0; k0 < 128; k0 += 16) {
        __syncthreads();
#pragma unroll
        for (int j = 0; j < 2; j++) {
            int idx = t + j * 256;
            int row = idx >> 2, k4 = (idx & 3) * 4;
            float4 v = *reinterpret_cast<const float4*>(
                &g_MH[(b * NSEQ + r0 + row) * 128 + k0 + k4]);
            sAT[(k4 + 0) * 132 + row] = v.x;
            sAT[(k4 + 1) * 132 + row] = v.y;
            sAT[(k4 + 2) * 132 + row] = v.z;
            sAT[(k4 + 3) * 132 + row] = v.w;
        }
#pragma unroll
        for (int j = 0; j < 2; j++) {
            int idx = t + j * 256;
            int c = idx >> 2, k4 = (idx & 3) * 4;
            int gi = (b * NSEQ + c0 + c) * 128 + k0 + k4;
            float4 vn = *reinterpret_cast<const float4*>(&nodes[gi]);
            float4 vg = *reinterpret_cast<const float4*>(&graph[gi]);
            sBT[(k4 + 0) * 132 + c] = vn.x + vg.x;
            sBT[(k4 + 1) * 132 + c] = vn.y + vg.y;
            sBT[(k4 + 2) * 132 + c] = vn.z + vg.z;
            sBT[(k4 + 3) * 132 + c] = vn.w + vg.w;
        }
        __syncthreads();
#pragma unroll
        for (int kk = 0; kk < 16; kk++) {
            float4 a0 = *reinterpret_cast<float4*>(&sAT[kk * 132 + ty * 8]);
            float4 a1 = *reinterpret_cast<float4*>(&sAT[kk * 132 + ty * 8 + 4]);
            float4 b0 = *reinterpret_cast<float4*>(&sBT[kk * 132 + tx * 8]);
            float4 b1 = *reinterpret_cast<float4*>(&sBT[kk * 132 + tx * 8 + 4]);
            float a[8] = {a0.x,a0.y,a0.z,a0.w,a1.x,a1.y,a1.z,a1.w};
            float bb[8] = {b0.x,b0.y,b0.z,b0.w,b1.x,b1.y,b1.z,b1.w};
#pragma unroll
            for (int i = 0; i < 8; i++)
#pragma unroll
                for (int j = 0; j < 8; j++)
                    acc[i][j] = fmaf(a[i], bb[j], acc[i][j]);
        }
    }

    const float inv_sqrt_emb = 0.08838834764831845f;  // 1/sqrt(128)
#pragma unroll
    for (int i = 0; i < 8; i++) {
        int r = r0 + ty * 8 + i;
        int gbase = (b * NSEQ + r) * NSEQ + c0 + tx * 8;
        float4 m0 = *reinterpret_cast<const float4*>(&mask[gbase]);
        float4 m1 = *reinterpret_cast<const float4*>(&mask[gbase + 4]);
        float4 o0, o1;
        o0.x = fmaf(10.f, fast_tanh(acc[i][0] * inv_sqrt_emb), m0.x);
        o0.y = fmaf(10.f, fast_tanh(acc[i][1] * inv_sqrt_emb), m0.y);
        o0.z = fmaf(10.f, fast_tanh(acc[i][2] * inv_sqrt_emb), m0.z);
        o0.w = fmaf(10.f, fast_tanh(acc[i][3] * inv_sqrt_emb), m0.w);
        o1.x = fmaf(10.f, fast_tanh(acc[i][4] * inv_sqrt_emb), m1.x);
        o1.y = fmaf(10.f, fast_tanh(acc[i][5] * inv_sqrt_emb), m1.y);
        o1.z = fmaf(10.f, fast_tanh(acc[i][6] * inv_sqrt_emb), m1.z);
        o1.w = fmaf(10.f, fast_tanh(acc[i][7] * inv_sqrt_emb), m1.w);
        *reinterpret_cast<float4*>(&out[gbase])     = o0;
        *reinterpret_cast<float4*>(&out[gbase + 4]) = o1;
    }
}

// ---------------- in-place row softmax over d_out ----------------
__global__ void softmax_kernel(float* __restrict__ out) {
    float4* p = reinterpret_cast<float4*>(out + (size_t)blockIdx.x * NSEQ);
    int t = threadIdx.x;  // 128 threads
    float4 v = p[t];
    float mx = fmaxf(fmaxf(v.x, v.y), fmaxf(v.z, v.w));
#pragma unroll
    for (int o = 16; o; o >>= 1) mx = fmaxf(mx, __shfl_xor_sync(0xffffffffu, mx, o));
    __shared__ float sm[4];
    if ((t & 31) == 0) sm[t >> 5] = mx;
    __syncthreads();
    mx = fmaxf(fmaxf(sm[0], sm[1]), fmaxf(sm[2], sm[3]));

    v.x = __expf(v.x - mx); v.y = __expf(v.y - mx);
    v.z = __expf(v.z - mx); v.w = __expf(v.w - mx);
    float sum = v.x + v.y + v.z + v.w;
#pragma unroll
    for (int o = 16; o; o >>= 1) sum += __shfl_xor_sync(0xffffffffu, sum, o);
    __shared__ float ss[4];
    if ((t & 31) == 0) ss[t >> 5] = sum;
    __syncthreads();
    sum = ss[0] + ss[1] + ss[2] + ss[3];

    float inv = 1.f / sum;
    v.x *= inv; v.y *= inv; v.z *= inv; v.w *= inv;
    p[t] = v;
}

// ---------------- launch ----------------
extern "C" void kernel_launch(void* const* d_in, const int* in_sizes, int n_in,
                              void* d_out, int out_size) {
    const float* enc_nodes = (const float*)d_in[0];
    const float* enc_graph = (const float*)d_in[1];
    const float* enc_q1    = (const float*)d_in[2];
    const float* enc_fg    = (const float*)d_in[3];
    const float* enc_ln    = (const float*)d_in[4];
    const float* enc_lg    = (const float*)d_in[5];
    const float* mask      = (const float*)d_in[6];
    const float* Wq_first  = (const float*)d_in[7];
    const float* Wq_last   = (const float*)d_in[8];
    const float* Wk        = (const float*)d_in[9];
    const float* Wv        = (const float*)d_in[10];
    const float* Wq_first_e= (const float*)d_in[11];
    const float* Wq_last_e = (const float*)d_in[12];
    const float* Wk_e      = (const float*)d_in[13];
    const float* Wv_e      = (const float*)d_in[14];
    const float* Wcomb1    = (const float*)d_in[15];
    const float* bcomb1    = (const float*)d_in[16];
    const float* Wcomb2    = (const float*)d_in[17];
    const float* bcomb2    = (const float*)d_in[18];
    float* out = (float*)d_out;

    proj4_kernel<<<dim3(128, 4), 256>>>(enc_nodes, enc_graph, Wk, Wv, Wk_e, Wv_e);
    qproj_kernel<<<256, 256>>>(enc_q1, Wq_first, enc_ln, Wq_last,
                               enc_fg, Wq_first_e, enc_lg, Wq_last_e);
    attn_kernel<<<dim3(2, NHEAD, BATCH), 128>>>(mask);
    comb_kernel<<<256, 256>>>(Wcomb1, bcomb1, Wcomb2, bcomb2);
    score_kernel<<<dim3(4, 4, BATCH), 256>>>(enc_nodes, enc_graph, mask, out);
    softmax_kernel<<<BATCH * NSEQ, 128>>>(out);
}

// round 3
// speedup vs baseline: 1.8046x; 1.4985x over previous
#include <cuda_runtime.h>
#include <cuda_bf16.h>
#include <math.h>
#include <stdint.h>

#define BATCH 32
#define NSEQ  512
#define EMB   128
#define NHEAD 8
#define HDIM  16

// ---------------- scratch (no allocations allowed) ----------------
__device__ float g_K [BATCH*NSEQ*EMB];
__device__ float g_V [BATCH*NSEQ*EMB];
__device__ float g_Ke[BATCH*NSEQ*EMB];
__device__ float g_Ve[BATCH*NSEQ*EMB];
__device__ float g_Q [BATCH*NSEQ*EMB];
__device__ float g_O1[BATCH*NSEQ*EMB];
__device__ float g_O2[BATCH*NSEQ*EMB];
__device__ float g_MH[BATCH*NSEQ*EMB];

__device__ __forceinline__ float fast_tanh(float x) {
    float e = __expf(2.f * x);
    return 1.f - __fdividef(2.f, e + 1.f);
}

// bf16 hi/lo split of a float pair, packed as bf16x2 (low half = first elem)
__device__ __forceinline__ void split2(float x, float y, uint32_t& h, uint32_t& l) {
    __nv_bfloat162 hv(__float2bfloat16(x), __float2bfloat16(y));
    h = *reinterpret_cast<uint32_t*>(&hv);
    __nv_bfloat162 lv(__float2bfloat16(x - __bfloat162float(hv.x)),
                      __float2bfloat16(y - __bfloat162float(hv.y)));
    l = *reinterpret_cast<uint32_t*>(&lv);
}

__device__ __forceinline__ void mma_bf16(float* d,
        uint32_t a0, uint32_t a1, uint32_t a2, uint32_t a3,
        uint32_t b0, uint32_t b1) {
    asm volatile(
        "mma.sync.aligned.m16n8k16.row.col.f32.bf16.bf16.f32 "
        "{%0,%1,%2,%3}, {%4,%5,%6,%7}, {%8,%9}, {%0,%1,%2,%3};"
        : "+f"(d[0]), "+f"(d[1]), "+f"(d[2]), "+f"(d[3])
        : "r"(a0), "r"(a1), "r"(a2), "r"(a3), "r"(b0), "r"(b1));
}

// ======================================================================
// proj4: K/V/Ke/Ve projections. 128x128 tile, 8x8 microtile, BK=16.
// grid (128, 4), block 256.
// ======================================================================
__global__ void __launch_bounds__(256) proj4_kernel(
        const float* __restrict__ nodes, const float* __restrict__ graph,
        const float* __restrict__ Wk, const float* __restrict__ Wv,
        const float* __restrict__ Wke, const float* __restrict__ Wve) {
    __shared__ float sAT[16 * 132];
    __shared__ float sB [16 * 128];
    int z = blockIdx.y;
    const float* X = (z < 2) ? nodes : graph;
    const float* W = (z == 0) ? Wk : (z == 1) ? Wv : (z == 2) ? Wke : Wve;
    float* Out = (z == 0) ? g_K : (z == 1) ? g_V : (z == 2) ? g_Ke : g_Ve;

    int t = threadIdx.x;
    int tx = t & 15, ty = t >> 4;
    int row0 = blockIdx.x * 128;

    float acc[8][8];
#pragma unroll
    for (int i = 0; i < 8; i++)
#pragma unroll
        for (int j = 0; j < 8; j++) acc[i][j] = 0.f;

    for (int k0 = 0; k0 < 128; k0 += 16) {
        __syncthreads();
#pragma unroll
        for (int j = 0; j < 2; j++) {
            int idx = t + j * 256;
            int row = idx >> 2, k4 = (idx & 3) * 4;
            float4 v = *reinterpret_cast<const float4*>(&X[(row0 + row) * 128 + k0 + k4]);
            sAT[(k4 + 0) * 132 + row] = v.x;
            sAT[(k4 + 1) * 132 + row] = v.y;
            sAT[(k4 + 2) * 132 + row] = v.z;
            sAT[(k4 + 3) * 132 + row] = v.w;
        }
#pragma unroll
        for (int j = 0; j < 2; j++) {
            int idx = t + j * 256;
            int kk = idx >> 5, c4 = (idx & 31) * 4;
            *reinterpret_cast<float4*>(&sB[kk * 128 + c4]) =
                *reinterpret_cast<const float4*>(&W[(k0 + kk) * 128 + c4]);
        }
        __syncthreads();
#pragma unroll
        for (int kk = 0; kk < 16; kk++) {
            float4 a0 = *reinterpret_cast<float4*>(&sAT[kk * 132 + ty * 8]);
            float4 a1 = *reinterpret_cast<float4*>(&sAT[kk * 132 + ty * 8 + 4]);
            float4 b0 = *reinterpret_cast<float4*>(&sB [kk * 128 + tx * 8]);
            float4 b1 = *reinterpret_cast<float4*>(&sB [kk * 128 + tx * 8 + 4]);
            float a[8] = {a0.x,a0.y,a0.z,a0.w,a1.x,a1.y,a1.z,a1.w};
            float b[8] = {b0.x,b0.y,b0.z,b0.w,b1.x,b1.y,b1.z,b1.w};
#pragma unroll
            for (int i = 0; i < 8; i++)
#pragma unroll
                for (int j = 0; j < 8; j++)
                    acc[i][j] = fmaf(a[i], b[j], acc[i][j]);
        }
    }
#pragma unroll
    for (int i = 0; i < 8; i++) {
        int r = row0 + ty * 8 + i;
        *reinterpret_cast<float4*>(&Out[r * 128 + tx * 8]) =
            make_float4(acc[i][0], acc[i][1], acc[i][2], acc[i][3]);
        *reinterpret_cast<float4*>(&Out[r * 128 + tx * 8 + 4]) =
            make_float4(acc[i][4], acc[i][5], acc[i][6], acc[i][7]);
    }
}

// ======================================================================
// qproj: g_Q = sum_{p} Xp @ Wp.  64x128 tile, 4x8 micro, BK=16.
// ======================================================================
__global__ void __launch_bounds__(256) qproj_kernel(
        const float* __restrict__ X0, const float* __restrict__ W0,
        const float* __restrict__ X1, const float* __restrict__ W1,
        const float* __restrict__ X2, const float* __restrict__ W2,
        const float* __restrict__ X3, const float* __restrict__ W3) {
    __shared__ float sAT[16 * 68];
    __shared__ float sB [16 * 128];
    int t = threadIdx.x;
    int tx = t & 15, ty = t >> 4;
    int row0 = blockIdx.x * 64;

    float acc[4][8];
#pragma unroll
    for (int i = 0; i < 4; i++)
#pragma unroll
        for (int j = 0; j < 8; j++) acc[i][j] = 0.f;

    const float* Xs[4] = {X0, X1, X2, X3};
    const float* Ws[4] = {W0, W1, W2, W3};

    for (int p = 0; p < 4; p++) {
        const float* X = Xs[p];
        const float* W = Ws[p];
        for (int k0 = 0; k0 < 128; k0 += 16) {
            __syncthreads();
            {
                int row = t >> 2, k4 = (t & 3) * 4;
                float4 v = *reinterpret_cast<const float4*>(&X[(row0 + row) * 128 + k0 + k4]);
                sAT[(k4 + 0) * 68 + row] = v.x;
                sAT[(k4 + 1) * 68 + row] = v.y;
                sAT[(k4 + 2) * 68 + row] = v.z;
                sAT[(k4 + 3) * 68 + row] = v.w;
            }
#pragma unroll
            for (int j = 0; j < 2; j++) {
                int idx = t + j * 256;
                int kk = idx >> 5, c4 = (idx & 31) * 4;
                *reinterpret_cast<float4*>(&sB[kk * 128 + c4]) =
                    *reinterpret_cast<const float4*>(&W[(k0 + kk) * 128 + c4]);
            }
            __syncthreads();
#pragma unroll
            for (int kk = 0; kk < 16; kk++) {
                float4 a0 = *reinterpret_cast<float4*>(&sAT[kk * 68 + ty * 4]);
                float4 b0 = *reinterpret_cast<float4*>(&sB [kk * 128 + tx * 8]);
                float4 b1 = *reinterpret_cast<float4*>(&sB [kk * 128 + tx * 8 + 4]);
                float a[4] = {a0.x,a0.y,a0.z,a0.w};
                float b[8] = {b0.x,b0.y,b0.z,b0.w,b1.x,b1.y,b1.z,b1.w};
#pragma unroll
                for (int i = 0; i < 4; i++)
#pragma unroll
                    for (int j = 0; j < 8; j++)
                        acc[i][j] = fmaf(a[i], b[j], acc[i][j]);
            }
        }
    }
#pragma unroll
    for (int i = 0; i < 4; i++) {
        int r = row0 + ty * 4 + i;
        *reinterpret_cast<float4*>(&g_Q[r * 128 + tx * 8]) =
            make_float4(acc[i][0], acc[i][1], acc[i][2], acc[i][3]);
        *reinterpret_cast<float4*>(&g_Q[r * 128 + tx * 8 + 4]) =
            make_float4(acc[i][4], acc[i][5], acc[i][6], acc[i][7]);
    }
}

// ======================================================================
// comb: g_MH = g_O1@W1 + b1 + g_O2@W2 + b2.  64x128 tile, 4x8 micro.
// ======================================================================
__global__ void __launch_bounds__(256) comb_kernel(
        const float* __restrict__ W1, const float* __restrict__ b1,
        const float* __restrict__ W2, const float* __restrict__ b2) {
    __shared__ float sAT[16 * 68];
    __shared__ float sB [16 * 128];
    int t = threadIdx.x;
    int tx = t & 15, ty = t >> 4;
    int row0 = blockIdx.x * 64;

    float acc[4][8];
#pragma unroll
    for (int i = 0; i < 4; i++)
#pragma unroll
        for (int j = 0; j < 8; j++) acc[i][j] = 0.f;

    const float* Xs[2] = {g_O1, g_O2};
    const float* Ws[2] = {W1, W2};

    for (int p = 0; p < 2; p++) {
        const float* X = Xs[p];
        const float* W = Ws[p];
        for (int k0 = 0; k0 < 128; k0 += 16) {
            __syncthreads();
            {
                int row = t >> 2, k4 = (t & 3) * 4;
                float4 v = *reinterpret_cast<const float4*>(&X[(row0 + row) * 128 + k0 + k4]);
                sAT[(k4 + 0) * 68 + row] = v.x;
                sAT[(k4 + 1) * 68 + row] = v.y;
                sAT[(k4 + 2) * 68 + row] = v.z;
                sAT[(k4 + 3) * 68 + row] = v.w;
            }
#pragma unroll
            for (int j = 0; j < 2; j++) {
                int idx = t + j * 256;
                int kk = idx >> 5, c4 = (idx & 31) * 4;
                *reinterpret_cast<float4*>(&sB[kk * 128 + c4]) =
                    *reinterpret_cast<const float4*>(&W[(k0 + kk) * 128 + c4]);
            }
            __syncthreads();
#pragma unroll
            for (int kk = 0; kk < 16; kk++) {
                float4 a0 = *reinterpret_cast<float4*>(&sAT[kk * 68 + ty * 4]);
                float4 b0 = *reinterpret_cast<float4*>(&sB [kk * 128 + tx * 8]);
                float4 b1 = *reinterpret_cast<float4*>(&sB [kk * 128 + tx * 8 + 4]);
                float a[4] = {a0.x,a0.y,a0.z,a0.w};
                float b[8] = {b0.x,b0.y,b0.z,b0.w,b1.x,b1.y,b1.z,b1.w};
#pragma unroll
                for (int i = 0; i < 4; i++)
#pragma unroll
                    for (int j = 0; j < 8; j++)
                        acc[i][j] = fmaf(a[i], b[j], acc[i][j]);
            }
        }
    }
    float bias[8];
#pragma unroll
    for (int j = 0; j < 8; j++) bias[j] = b1[tx * 8 + j] + b2[tx * 8 + j];
#pragma unroll
    for (int i = 0; i < 4; i++) {
        int r = row0 + ty * 4 + i;
        *reinterpret_cast<float4*>(&g_MH[r * 128 + tx * 8]) =
            make_float4(acc[i][0]+bias[0], acc[i][1]+bias[1], acc[i][2]+bias[2], acc[i][3]+bias[3]);
        *reinterpret_cast<float4*>(&g_MH[r * 128 + tx * 8 + 4]) =
            make_float4(acc[i][4]+bias[4], acc[i][5]+bias[5], acc[i][6]+bias[6], acc[i][7]+bias[7]);
    }
}

// ======================================================================
// dual attention via m16n8k16 bf16 MMA with hi/lo split (3-mma products).
// grid (4, NHEAD, BATCH), block 256 (8 warps x 16 rows = 128 rows).
// Keys processed in chunks of 32. No running max (scores bounded; clamp 60).
// ======================================================================
__global__ void __launch_bounds__(256) attn_kernel(const float* __restrict__ mask) {
    // K tiles: [32 keys][8 u32 bf16x2 d-pairs], row stride 9 (pad)
    __shared__ uint32_t sKh[32 * 9],  sKl[32 * 9];
    __shared__ uint32_t sKeh[32 * 9], sKel[32 * 9];
    // V transposed: bf16 [16 d][40 keys-padded] -> u32 reads of key-pairs
    __shared__ __nv_bfloat16 sVh[16 * 40],  sVl[16 * 40];
    __shared__ __nv_bfloat16 sVeh[16 * 40], sVel[16 * 40];

    int t = threadIdx.x;
    int lane = t & 31, wid = t >> 5;
    int g = lane >> 2, tq = lane & 3;
    int b = blockIdx.z, h = blockIdx.y;
    int r0 = blockIdx.x * 128;
    int rw = wid * 16;

    // ---- Q fragments (persistent, hi/lo) ----
    uint32_t qh[4], ql[4];
    {
        const float* qp = g_Q + ((size_t)(b * NSEQ + r0 + rw + g) * EMB + h * HDIM);
        float2 v;
        v = *reinterpret_cast<const float2*>(qp + 2 * tq);                 split2(v.x, v.y, qh[0], ql[0]);
        v = *reinterpret_cast<const float2*>(qp + 8 * EMB + 2 * tq);       split2(v.x, v.y, qh[1], ql[1]);
        v = *reinterpret_cast<const float2*>(qp + 2 * tq + 8);             split2(v.x, v.y, qh[2], ql[2]);
        v = *reinterpret_cast<const float2*>(qp + 8 * EMB + 2 * tq + 8);   split2(v.x, v.y, qh[3], ql[3]);
    }

    float o1[2][4] = {{0,0,0,0},{0,0,0,0}};
    float o2[2][4] = {{0,0,0,0},{0,0,0,0}};
    float la1 = 0.f, lb1 = 0.f, la2 = 0.f, lb2 = 0.f;

    // staging indices
    int sidx = t & 127;
    int sm = sidx >> 2, sd4 = (sidx & 3) * 4;
    bool first_half = (t < 128);

    const float* maskrow0 = mask + ((size_t)(b * NSEQ + r0 + rw + g) * NSEQ);
    const float* maskrow1 = maskrow0 + 8 * NSEQ;

    for (int c0 = 0; c0 < NSEQ; c0 += 32) {
        __syncthreads();
        // ---- stage K (or Ke) ----
        {
            const float* src = first_half ? g_K : g_Ke;
            uint32_t* dh = first_half ? sKh : sKeh;
            uint32_t* dl = first_half ? sKl : sKel;
            float4 v = *reinterpret_cast<const float4*>(
                src + ((size_t)(b * NSEQ + c0 + sm) * EMB + h * HDIM + sd4));
            uint32_t h0, l0, h1, l1;
            split2(v.x, v.y, h0, l0);
            split2(v.z, v.w, h1, l1);
            dh[sm * 9 + sd4 / 2]     = h0;
            dh[sm * 9 + sd4 / 2 + 1] = h1;
            dl[sm * 9 + sd4 / 2]     = l0;
            dl[sm * 9 + sd4 / 2 + 1] = l1;
        }
        // ---- stage V (or Ve) transposed ----
        {
            const float* src = first_half ? g_V : g_Ve;
            __nv_bfloat16* dh = first_half ? sVh : sVeh;
            __nv_bfloat16* dl = first_half ? sVl : sVel;
            float4 v = *reinterpret_cast<const float4*>(
                src + ((size_t)(b * NSEQ + c0 + sm) * EMB + h * HDIM + sd4));
            float vv[4] = {v.x, v.y, v.z, v.w};
#pragma unroll
            for (int j = 0; j < 4; j++) {
                __nv_bfloat16 hi = __float2bfloat16(vv[j]);
                __nv_bfloat16 lo = __float2bfloat16(vv[j] - __bfloat162float(hi));
                dh[(sd4 + j) * 40 + sm] = hi;
                dl[(sd4 + j) * 40 + sm] = lo;
            }
        }
        __syncthreads();

        // ---- S = Q K^T for both attentions (4 n-tiles of 8 cols each) ----
        float S1[4][4], S2[4][4];
#pragma unroll
        for (int nt = 0; nt < 4; nt++) {
#pragma unroll
            for (int j = 0; j < 4; j++) { S1[nt][j] = 0.f; S2[nt][j] = 0.f; }
            int mrow = nt * 8 + g;
            uint32_t b0h = sKh[mrow * 9 + tq],     b1h = sKh[mrow * 9 + tq + 4];
            uint32_t b0l = sKl[mrow * 9 + tq],     b1l = sKl[mrow * 9 + tq + 4];
            mma_bf16(S1[nt], qh[0], qh[1], qh[2], qh[3], b0h, b1h);
            mma_bf16(S1[nt], qh[0], qh[1], qh[2], qh[3], b0l, b1l);
            mma_bf16(S1[nt], ql[0], ql[1], ql[2], ql[3], b0h, b1h);
            uint32_t e0h = sKeh[mrow * 9 + tq],    e1h = sKeh[mrow * 9 + tq + 4];
            uint32_t e0l = sKel[mrow * 9 + tq],    e1l = sKel[mrow * 9 + tq + 4];
            mma_bf16(S2[nt], qh[0], qh[1], qh[2], qh[3], e0h, e1h);
            mma_bf16(S2[nt], qh[0], qh[1], qh[2], qh[3], e0l, e1l);
            mma_bf16(S2[nt], ql[0], ql[1], ql[2], ql[3], e0h, e1h);
        }

        // ---- epilogue: p = exp(s/4 + mask), accumulate row sums ----
#pragma unroll
        for (int nt = 0; nt < 4; nt++) {
            int cc = c0 + nt * 8 + tq * 2;
            float2 m0 = *reinterpret_cast<const float2*>(maskrow0 + cc);
            float2 m1 = *reinterpret_cast<const float2*>(maskrow1 + cc);
            float p;
            p = __expf(fminf(fmaf(S1[nt][0], 0.25f, m0.x), 60.f)); S1[nt][0] = p; la1 += p;
            p = __expf(fminf(fmaf(S1[nt][1], 0.25f, m0.y), 60.f)); S1[nt][1] = p; la1 += p;
            p = __expf(fminf(fmaf(S1[nt][2], 0.25f, m1.x), 60.f)); S1[nt][2] = p; lb1 += p;
            p = __expf(fminf(fmaf(S1[nt][3], 0.25f, m1.y), 60.f)); S1[nt][3] = p; lb1 += p;
            p = __expf(fminf(fmaf(S2[nt][0], 0.25f, m0.x), 60.f)); S2[nt][0] = p; la2 += p;
            p = __expf(fminf(fmaf(S2[nt][1], 0.25f, m0.y), 60.f)); S2[nt][1] = p; la2 += p;
            p = __expf(fminf(fmaf(S2[nt][2], 0.25f, m1.x), 60.f)); S2[nt][2] = p; lb2 += p;
            p = __expf(fminf(fmaf(S2[nt][3], 0.25f, m1.y), 60.f)); S2[nt][3] = p; lb2 += p;
        }

        // ---- O += P V  (k = 32 keys -> 2 k16 steps; 2 d-tiles of 8) ----
#pragma unroll
        for (int ks = 0; ks < 2; ks++) {
            uint32_t a1h[4], a1l[4], a2h[4], a2l[4];
            split2(S1[2*ks][0],   S1[2*ks][1],   a1h[0], a1l[0]);
            split2(S1[2*ks][2],   S1[2*ks][3],   a1h[1], a1l[1]);
            split2(S1[2*ks+1][0], S1[2*ks+1][1], a1h[2], a1l[2]);
            split2(S1[2*ks+1][2], S1[2*ks+1][3], a1h[3], a1l[3]);
            split2(S2[2*ks][0],   S2[2*ks][1],   a2h[0], a2l[0]);
            split2(S2[2*ks][2],   S2[2*ks][3],   a2h[1], a2l[1]);
            split2(S2[2*ks+1][0], S2[2*ks+1][1], a2h[2], a2l[2]);
            split2(S2[2*ks+1][2], S2[2*ks+1][3], a2h[3], a2l[3]);
#pragma unroll
            for (int dt = 0; dt < 2; dt++) {
                int d = dt * 8 + g;
                int m0i = (ks * 8 + tq) * 2, m1i = (ks * 8 + 4 + tq) * 2;
                uint32_t vb0h = *reinterpret_cast<uint32_t*>(&sVh[d * 40 + m0i]);
                uint32_t vb1h = *reinterpret_cast<uint32_t*>(&sVh[d * 40 + m1i]);
                uint32_t vb0l = *reinterpret_cast<uint32_t*>(&sVl[d * 40 + m0i]);
                uint32_t vb1l = *reinterpret_cast<uint32_t*>(&sVl[d * 40 + m1i]);
                mma_bf16(o1[dt], a1h[0], a1h[1], a1h[2], a1h[3], vb0h, vb1h);
                mma_bf16(o1[dt], a1h[0], a1h[1], a1h[2], a1h[3], vb0l, vb1l);
                mma_bf16(o1[dt], a1l[0], a1l[1], a1l[2], a1l[3], vb0h, vb1h);
                uint32_t wb0h = *reinterpret_cast<uint32_t*>(&sVeh[d * 40 + m0i]);
                uint32_t wb1h = *reinterpret_cast<uint32_t*>(&sVeh[d * 40 + m1i]);
                uint32_t wb0l = *reinterpret_cast<uint32_t*>(&sVel[d * 40 + m0i]);
                uint32_t wb1l = *reinterpret_cast<uint32_t*>(&sVel[d * 40 + m1i]);
                mma_bf16(o2[dt], a2h[0], a2h[1], a2h[2], a2h[3], wb0h, wb1h);
                mma_bf16(o2[dt], a2h[0], a2h[1], a2h[2], a2h[3], wb0l, wb1l);
                mma_bf16(o2[dt], a2l[0], a2l[1], a2l[2], a2l[3], wb0h, wb1h);
            }
        }
    }

    // ---- reduce row sums across the quad (lanes sharing lane>>2) ----
    la1 += __shfl_xor_sync(0xffffffffu, la1, 1); la1 += __shfl_xor_sync(0xffffffffu, la1, 2);
    lb1 += __shfl_xor_sync(0xffffffffu, lb1, 1); lb1 += __shfl_xor_sync(0xffffffffu, lb1, 2);
    la2 += __shfl_xor_sync(0xffffffffu, la2, 1); la2 += __shfl_xor_sync(0xffffffffu, la2, 2);
    lb2 += __shfl_xor_sync(0xffffffffu, lb2, 1); lb2 += __shfl_xor_sync(0xffffffffu, lb2, 2);
    float ia1 = 1.f / la1, ib1 = 1.f / lb1, ia2 = 1.f / la2, ib2 = 1.f / lb2;

    // ---- store O ----
    {
        size_t base0 = (size_t)(b * NSEQ + r0 + rw + g) * EMB + h * HDIM;
        size_t base1 = base0 + 8 * EMB;
#pragma unroll
        for (int dt = 0; dt < 2; dt++) {
            int dcol = dt * 8 + tq * 2;
            *reinterpret_cast<float2*>(g_O1 + base0 + dcol) = make_float2(o1[dt][0] * ia1, o1[dt][1] * ia1);
            *reinterpret_cast<float2*>(g_O1 + base1 + dcol) = make_float2(o1[dt][2] * ib1, o1[dt][3] * ib1);
            *reinterpret_cast<float2*>(g_O2 + base0 + dcol) = make_float2(o2[dt][0] * ia2, o2[dt][1] * ia2);
            *reinterpret_cast<float2*>(g_O2 + base1 + dcol) = make_float2(o2[dt][2] * ib2, o2[dt][3] * ib2);
        }
    }
}

// ======================================================================
// score: logits = 10*tanh((g_MH @ shk^T)/sqrt(128)) + mask
// 128x128 tile, 8x8 micro, BK=16. grid (4, 4, BATCH), block 256.
// ======================================================================
__global__ void __launch_bounds__(256) score_kernel(
        const float* __restrict__ nodes, const float* __restrict__ graph,
        const float* __restrict__ mask, float* __restrict__ out) {
    __shared__ float sAT[16 * 132];
    __shared__ float sBT[16 * 132];
    int t = threadIdx.x;
    int tx = t & 15, ty = t >> 4;
    int b = blockIdx.z;
    int c0 = blockIdx.x * 128, r0 = blockIdx.y * 128;

    float acc[8][8];
#pragma unroll
    for (int i = 0; i < 8; i++)
#pragma unroll
        for (int j = 0; j < 8; j++) acc[i][j] = 0.f;

    for (int k0 = 0; k0 < 128; k0 += 16) {
        __syncthreads();
#pragma unroll
        for (int j = 0; j < 2; j++) {
            int idx = t + j * 256;
            int row = idx >> 2, k4 = (idx & 3) * 4;
            float4 v = *reinterpret_cast<const float4*>(
                &g_MH[(b * NSEQ + r0 + row) * 128 + k0 + k4]);
            sAT[(k4 + 0) * 132 + row] = v.x;
            sAT[(k4 + 1) * 132 + row] = v.y;
            sAT[(k4 + 2) * 132 + row] = v.z;
            sAT[(k4 + 3) * 132 + row] = v.w;
        }
#pragma unroll
        for (int j = 0; j < 2; j++) {
            int idx = t + j * 256;
            int c = idx >> 2, k4 = (idx & 3) * 4;
            int gi = (b * NSEQ + c0 + c) * 128 + k0 + k4;
            float4 vn = *reinterpret_cast<const float4*>(&nodes[gi]);
            float4 vg = *reinterpret_cast<const float4*>(&graph[gi]);
            sBT[(k4 + 0) * 132 + c] = vn.x + vg.x;
            sBT[(k4 + 1) * 132 + c] = vn.y + vg.y;
            sBT[(k4 + 2) * 132 + c] = vn.z + vg.z;
            sBT[(k4 + 3) * 132 + c] = vn.w + vg.w;
        }
        __syncthreads();
#pragma unroll
        for (int kk = 0; kk < 16; kk++) {
            float4 a0 = *reinterpret_cast<float4*>(&sAT[kk * 132 + ty * 8]);
            float4 a1 = *reinterpret_cast<float4*>(&sAT[kk * 132 + ty * 8 + 4]);
            float4 b0 = *reinterpret_cast<float4*>(&sBT[kk * 132 + tx * 8]);
            float4 b1 = *reinterpret_cast<float4*>(&sBT[kk * 132 + tx * 8 + 4]);
            float a[8] = {a0.x,a0.y,a0.z,a0.w,a1.x,a1.y,a1.z,a1.w};
            float bb[8] = {b0.x,b0.y,b0.z,b0.w,b1.x,b1.y,b1.z,b1.w};
#pragma unroll
            for (int i = 0; i < 8; i++)
#pragma unroll
                for (int j = 0; j < 8; j++)
                    acc[i][j] = fmaf(a[i], bb[j], acc[i][j]);
        }
    }

    const float inv_sqrt_emb = 0.08838834764831845f;  // 1/sqrt(128)
#pragma unroll
    for (int i = 0; i < 8; i++) {
        int r = r0 + ty * 8 + i;
        int gbase = (b * NSEQ + r) * NSEQ + c0 + tx * 8;
        float4 m0 = *reinterpret_cast<const float4*>(&mask[gbase]);
        float4 m1 = *reinterpret_cast<const float4*>(&mask[gbase + 4]);
        float4 o0, o1;
        o0.x = fmaf(10.f, fast_tanh(acc[i][0] * inv_sqrt_emb), m0.x);
        o0.y = fmaf(10.f, fast_tanh(acc[i][1] * inv_sqrt_emb), m0.y);
        o0.z = fmaf(10.f, fast_tanh(acc[i][2] * inv_sqrt_emb), m0.z);
        o0.w = fmaf(10.f, fast_tanh(acc[i][3] * inv_sqrt_emb), m0.w);
        o1.x = fmaf(10.f, fast_tanh(acc[i][4] * inv_sqrt_emb), m1.x);
        o1.y = fmaf(10.f, fast_tanh(acc[i][5] * inv_sqrt_emb), m1.y);
        o1.z = fmaf(10.f, fast_tanh(acc[i][6] * inv_sqrt_emb), m1.z);
        o1.w = fmaf(10.f, fast_tanh(acc[i][7] * inv_sqrt_emb), m1.w);
        *reinterpret_cast<float4*>(&out[gbase])     = o0;
        *reinterpret_cast<float4*>(&out[gbase + 4]) = o1;
    }
}

// ---------------- in-place row softmax over d_out ----------------
__global__ void softmax_kernel(float* __restrict__ out) {
    float4* p = reinterpret_cast<float4*>(out + (size_t)blockIdx.x * NSEQ);
    int t = threadIdx.x;  // 128 threads
    float4 v = p[t];
    float mx = fmaxf(fmaxf(v.x, v.y), fmaxf(v.z, v.w));
#pragma unroll
    for (int o = 16; o; o >>= 1) mx = fmaxf(mx, __shfl_xor_sync(0xffffffffu, mx, o));
    __shared__ float sm[4];
    if ((t & 31) == 0) sm[t >> 5] = mx;
    __syncthreads();
    mx = fmaxf(fmaxf(sm[0], sm[1]), fmaxf(sm[2], sm[3]));

    v.x = __expf(v.x - mx); v.y = __expf(v.y - mx);
    v.z = __expf(v.z - mx); v.w = __expf(v.w - mx);
    float sum = v.x + v.y + v.z + v.w;
#pragma unroll
    for (int o = 16; o; o >>= 1) sum += __shfl_xor_sync(0xffffffffu, sum, o);
    __shared__ float ss[4];
    if ((t & 31) == 0) ss[t >> 5] = sum;
    __syncthreads();
    sum = ss[0] + ss[1] + ss[2] + ss[3];

    float inv = 1.f / sum;
    v.x *= inv; v.y *= inv; v.z *= inv; v.w *= inv;
    p[t] = v;
}

// ---------------- launch ----------------
extern "C" void kernel_launch(void* const* d_in, const int* in_sizes, int n_in,
                              void* d_out, int out_size) {
    const float* enc_nodes = (const float*)d_in[0];
    const float* enc_graph = (const float*)d_in[1];
    const float* enc_q1    = (const float*)d_in[2];
    const float* enc_fg    = (const float*)d_in[3];
    const float* enc_ln    = (const float*)d_in[4];
    const float* enc_lg    = (const float*)d_in[5];
    const float* mask      = (const float*)d_in[6];
    const float* Wq_first  = (const float*)d_in[7];
    const float* Wq_last   = (const float*)d_in[8];
    const float* Wk        = (const float*)d_in[9];
    const float* Wv        = (const float*)d_in[10];
    const float* Wq_first_e= (const float*)d_in[11];
    const float* Wq_last_e = (const float*)d_in[12];
    const float* Wk_e      = (const float*)d_in[13];
    const float* Wv_e      = (const float*)d_in[14];
    const float* Wcomb1    = (const float*)d_in[15];
    const float* bcomb1    = (const float*)d_in[16];
    const float* Wcomb2    = (const float*)d_in[17];
    const float* bcomb2    = (const float*)d_in[18];
    float* out = (float*)d_out;

    proj4_kernel<<<dim3(128, 4), 256>>>(enc_nodes, enc_graph, Wk, Wv, Wk_e, Wv_e);
    qproj_kernel<<<256, 256>>>(enc_q1, Wq_first, enc_ln, Wq_last,
                               enc_fg, Wq_first_e, enc_lg, Wq_last_e);
    attn_kernel<<<dim3(4, NHEAD, BATCH), 256>>>(mask);
    comb_kernel<<<256, 256>>>(Wcomb1, bcomb1, Wcomb2, bcomb2);
    score_kernel<<<dim3(4, 4, BATCH), 256>>>(enc_nodes, enc_graph, mask, out);
    softmax_kernel<<<BATCH * NSEQ, 128>>>(out);
}

// round 4
// speedup vs baseline: 2.4881x; 1.3788x over previous
#include <cuda_runtime.h>
#include <cuda_bf16.h>
#include <math.h>
#include <stdint.h>

#define BATCH 32
#define NSEQ  512
#define EMB   128
#define NHEAD 8
#define HDIM  16

// ---------------- scratch (no allocations allowed) ----------------
__device__ float g_K [BATCH*NSEQ*EMB];
__device__ float g_V [BATCH*NSEQ*EMB];
__device__ float g_Ke[BATCH*NSEQ*EMB];
__device__ float g_Ve[BATCH*NSEQ*EMB];
__device__ float g_Q [BATCH*NSEQ*EMB];
__device__ float g_O1[BATCH*NSEQ*EMB];
__device__ float g_O2[BATCH*NSEQ*EMB];
__device__ float g_MH[BATCH*NSEQ*EMB];

__device__ __forceinline__ float fast_tanh(float x) {
    float e = __expf(2.f * x);
    return 1.f - __fdividef(2.f, e + 1.f);
}

// bf16 hi/lo split of a float pair, packed as bf16x2 (low half = first elem)
__device__ __forceinline__ void split2(float x, float y, uint32_t& h, uint32_t& l) {
    __nv_bfloat162 hv(__float2bfloat16(x), __float2bfloat16(y));
    h = *reinterpret_cast<uint32_t*>(&hv);
    __nv_bfloat162 lv(__float2bfloat16(x - __bfloat162float(hv.x)),
                      __float2bfloat16(y - __bfloat162float(hv.y)));
    l = *reinterpret_cast<uint32_t*>(&lv);
}

__device__ __forceinline__ void mma_bf16(float* d,
        uint32_t a0, uint32_t a1, uint32_t a2, uint32_t a3,
        uint32_t b0, uint32_t b1) {
    asm volatile(
        "mma.sync.aligned.m16n8k16.row.col.f32.bf16.bf16.f32 "
        "{%0,%1,%2,%3}, {%4,%5,%6,%7}, {%8,%9}, {%0,%1,%2,%3};"
        : "+f"(d[0]), "+f"(d[1]), "+f"(d[2]), "+f"(d[3])
        : "r"(a0), "r"(a1), "r"(a2), "r"(a3), "r"(b0), "r"(b1));
}

// ======================================================================
// Shared GEMM machinery: 128xM-tile x 128-N, BK=16, hi/lo split MMA.
// smem layout: [row][k-pair], row stride 12 u32 (8 used + 4 pad).
// ======================================================================
#define SStr 12

// stage A tile: 128 rows x 16 k from row-major X (k contiguous)
__device__ __forceinline__ void stage_A(const float* __restrict__ X, int row0, int k0,
                                        int t, uint32_t* sh, uint32_t* sl) {
#pragma unroll
    for (int j = 0; j < 2; j++) {
        int idx = t + j * 256;
        int r = idx >> 2, k4 = (idx & 3) * 4;
        float4 v = *reinterpret_cast<const float4*>(&X[(size_t)(row0 + r) * 128 + k0 + k4]);
        uint32_t h0, l0, h1, l1;
        split2(v.x, v.y, h0, l0);
        split2(v.z, v.w, h1, l1);
        int base = r * SStr + (k4 >> 1);
        sh[base] = h0; sh[base + 1] = h1;
        sl[base] = l0; sl[base + 1] = l1;
    }
}

// stage A-style tile from sum of two sources (for score's shk = nodes+graph)
__device__ __forceinline__ void stage_A_sum(const float* __restrict__ X, const float* __restrict__ Y,
                                            int row0, int k0, int t, uint32_t* sh, uint32_t* sl) {
#pragma unroll
    for (int j = 0; j < 2; j++) {
        int idx = t + j * 256;
        int r = idx >> 2, k4 = (idx & 3) * 4;
        size_t gi = (size_t)(row0 + r) * 128 + k0 + k4;
        float4 v = *reinterpret_cast<const float4*>(&X[gi]);
        float4 w = *reinterpret_cast<const float4*>(&Y[gi]);
        uint32_t h0, l0, h1, l1;
        split2(v.x + w.x, v.y + w.y, h0, l0);
        split2(v.z + w.z, v.w + w.w, h1, l1);
        int base = r * SStr + (k4 >> 1);
        sh[base] = h0; sh[base + 1] = h1;
        sl[base] = l0; sl[base + 1] = l1;
    }
}

// stage W tile transposed: 16 k x 128 n row-major W -> smem [n][k-pair]
__device__ __forceinline__ void stage_W(const float* __restrict__ W, int k0,
                                        int t, uint32_t* sh, uint32_t* sl) {
    int kp = t & 7, n4 = (t >> 3) * 4;
    float4 v0 = *reinterpret_cast<const float4*>(&W[(size_t)(k0 + 2 * kp) * 128 + n4]);
    float4 v1 = *reinterpret_cast<const float4*>(&W[(size_t)(k0 + 2 * kp + 1) * 128 + n4]);
    float x0[4] = {v0.x, v0.y, v0.z, v0.w};
    float x1[4] = {v1.x, v1.y, v1.z, v1.w};
#pragma unroll
    for (int j = 0; j < 4; j++) {
        uint32_t h, l;
        split2(x0[j], x1[j], h, l);
        sh[(n4 + j) * SStr + kp] = h;
        sl[(n4 + j) * SStr + kp] = l;
    }
}

// one BK=16 compute step: warp handles rows [wid*16, wid*16+16), all 16 n-tiles
__device__ __forceinline__ void mma_step(const uint32_t* sAh, const uint32_t* sAl,
                                         const uint32_t* sBh, const uint32_t* sBl,
                                         int wid, int g, int tq, float acc[16][4]) {
    int m0 = wid * 16;
    uint32_t ah0 = sAh[(m0 + g) * SStr + tq],     ah1 = sAh[(m0 + 8 + g) * SStr + tq];
    uint32_t ah2 = sAh[(m0 + g) * SStr + tq + 4], ah3 = sAh[(m0 + 8 + g) * SStr + tq + 4];
    uint32_t al0 = sAl[(m0 + g) * SStr + tq],     al1 = sAl[(m0 + 8 + g) * SStr + tq];
    uint32_t al2 = sAl[(m0 + g) * SStr + tq + 4], al3 = sAl[(m0 + 8 + g) * SStr + tq + 4];
#pragma unroll
    for (int nt = 0; nt < 16; nt++) {
        uint32_t bh0 = sBh[(nt * 8 + g) * SStr + tq], bh1 = sBh[(nt * 8 + g) * SStr + tq + 4];
        uint32_t bl0 = sBl[(nt * 8 + g) * SStr + tq], bl1 = sBl[(nt * 8 + g) * SStr + tq + 4];
        mma_bf16(acc[nt], ah0, ah1, ah2, ah3, bh0, bh1);
        mma_bf16(acc[nt], ah0, ah1, ah2, ah3, bl0, bl1);
        mma_bf16(acc[nt], al0, al1, al2, al3, bh0, bh1);
    }
}

// ======================================================================
// proj4: K/V/Ke/Ve projections. grid (128, 4), block 256.
// ======================================================================
__global__ void __launch_bounds__(256) proj4_kernel(
        const float* __restrict__ nodes, const float* __restrict__ graph,
        const float* __restrict__ Wk, const float* __restrict__ Wv,
        const float* __restrict__ Wke, const float* __restrict__ Wve) {
    __shared__ uint32_t sAh[128 * SStr], sAl[128 * SStr];
    __shared__ uint32_t sBh[128 * SStr], sBl[128 * SStr];
    int z = blockIdx.y;
    const float* X = (z < 2) ? nodes : graph;
    const float* W = (z == 0) ? Wk : (z == 1) ? Wv : (z == 2) ? Wke : Wve;
    float* Out = (z == 0) ? g_K : (z == 1) ? g_V : (z == 2) ? g_Ke : g_Ve;

    int t = threadIdx.x;
    int lane = t & 31, wid = t >> 5;
    int g = lane >> 2, tq = lane & 3;
    int row0 = blockIdx.x * 128;

    float acc[16][4];
#pragma unroll
    for (int nt = 0; nt < 16; nt++)
#pragma unroll
        for (int j = 0; j < 4; j++) acc[nt][j] = 0.f;

    for (int k0 = 0; k0 < 128; k0 += 16) {
        __syncthreads();
        stage_A(X, row0, k0, t, sAh, sAl);
        stage_W(W, k0, t, sBh, sBl);
        __syncthreads();
        mma_step(sAh, sAl, sBh, sBl, wid, g, tq, acc);
    }

    size_t r_lo = (size_t)row0 + wid * 16 + g;
    size_t r_hi = r_lo + 8;
#pragma unroll
    for (int nt = 0; nt < 16; nt++) {
        int c = nt * 8 + tq * 2;
        *reinterpret_cast<float2*>(&Out[r_lo * 128 + c]) = make_float2(acc[nt][0], acc[nt][1]);
        *reinterpret_cast<float2*>(&Out[r_hi * 128 + c]) = make_float2(acc[nt][2], acc[nt][3]);
    }
}

// ======================================================================
// qproj: g_Q = sum_{p} Xp @ Wp. grid (128), block 256.
// ======================================================================
__global__ void __launch_bounds__(256) qproj_kernel(
        const float* __restrict__ X0, const float* __restrict__ W0,
        const float* __restrict__ X1, const float* __restrict__ W1,
        const float* __restrict__ X2, const float* __restrict__ W2,
        const float* __restrict__ X3, const float* __restrict__ W3) {
    __shared__ uint32_t sAh[128 * SStr], sAl[128 * SStr];
    __shared__ uint32_t sBh[128 * SStr], sBl[128 * SStr];
    int t = threadIdx.x;
    int lane = t & 31, wid = t >> 5;
    int g = lane >> 2, tq = lane & 3;
    int row0 = blockIdx.x * 128;

    float acc[16][4];
#pragma unroll
    for (int nt = 0; nt < 16; nt++)
#pragma unroll
        for (int j = 0; j < 4; j++) acc[nt][j] = 0.f;

    const float* Xs[4] = {X0, X1, X2, X3};
    const float* Ws[4] = {W0, W1, W2, W3};

    for (int p = 0; p < 4; p++) {
        const float* X = Xs[p];
        const float* W = Ws[p];
        for (int k0 = 0; k0 < 128; k0 += 16) {
            __syncthreads();
            stage_A(X, row0, k0, t, sAh, sAl);
            stage_W(W, k0, t, sBh, sBl);
            __syncthreads();
            mma_step(sAh, sAl, sBh, sBl, wid, g, tq, acc);
        }
    }

    size_t r_lo = (size_t)row0 + wid * 16 + g;
    size_t r_hi = r_lo + 8;
#pragma unroll
    for (int nt = 0; nt < 16; nt++) {
        int c = nt * 8 + tq * 2;
        *reinterpret_cast<float2*>(&g_Q[r_lo * 128 + c]) = make_float2(acc[nt][0], acc[nt][1]);
        *reinterpret_cast<float2*>(&g_Q[r_hi * 128 + c]) = make_float2(acc[nt][2], acc[nt][3]);
    }
}

// ======================================================================
// comb: g_MH = g_O1@W1 + b1 + g_O2@W2 + b2. grid (128), block 256.
// ======================================================================
__global__ void __launch_bounds__(256) comb_kernel(
        const float* __restrict__ W1, const float* __restrict__ b1,
        const float* __restrict__ W2, const float* __restrict__ b2) {
    __shared__ uint32_t sAh[128 * SStr], sAl[128 * SStr];
    __shared__ uint32_t sBh[128 * SStr], sBl[128 * SStr];
    int t = threadIdx.x;
    int lane = t & 31, wid = t >> 5;
    int g = lane >> 2, tq = lane & 3;
    int row0 = blockIdx.x * 128;

    float acc[16][4];
#pragma unroll
    for (int nt = 0; nt < 16; nt++)
#pragma unroll
        for (int j = 0; j < 4; j++) acc[nt][j] = 0.f;

    const float* Xs[2] = {g_O1, g_O2};
    const float* Ws[2] = {W1, W2};

    for (int p = 0; p < 2; p++) {
        const float* X = Xs[p];
        const float* W = Ws[p];
        for (int k0 = 0; k0 < 128; k0 += 16) {
            __syncthreads();
            stage_A(X, row0, k0, t, sAh, sAl);
            stage_W(W, k0, t, sBh, sBl);
            __syncthreads();
            mma_step(sAh, sAl, sBh, sBl, wid, g, tq, acc);
        }
    }

    size_t r_lo = (size_t)row0 + wid * 16 + g;
    size_t r_hi = r_lo + 8;
#pragma unroll
    for (int nt = 0; nt < 16; nt++) {
        int c = nt * 8 + tq * 2;
        float2 bb1 = *reinterpret_cast<const float2*>(&b1[c]);
        float2 bb2 = *reinterpret_cast<const float2*>(&b2[c]);
        float bx = bb1.x + bb2.x, by = bb1.y + bb2.y;
        *reinterpret_cast<float2*>(&g_MH[r_lo * 128 + c]) =
            make_float2(acc[nt][0] + bx, acc[nt][1] + by);
        *reinterpret_cast<float2*>(&g_MH[r_hi * 128 + c]) =
            make_float2(acc[nt][2] + bx, acc[nt][3] + by);
    }
}

// ======================================================================
// score: logits = 10*tanh((g_MH @ shk^T)/sqrt(128)) + mask
// grid (4, 4, BATCH), block 256. B=shk rows are k-contiguous (A-style).
// ======================================================================
__global__ void __launch_bounds__(256) score_kernel(
        const float* __restrict__ nodes, const float* __restrict__ graph,
        const float* __restrict__ mask, float* __restrict__ out) {
    __shared__ uint32_t sAh[128 * SStr], sAl[128 * SStr];
    __shared__ uint32_t sBh[128 * SStr], sBl[128 * SStr];
    int t = threadIdx.x;
    int lane = t & 31, wid = t >> 5;
    int g = lane >> 2, tq = lane & 3;
    int b = blockIdx.z;
    int c0 = blockIdx.x * 128, r0 = blockIdx.y * 128;

    float acc[16][4];
#pragma unroll
    for (int nt = 0; nt < 16; nt++)
#pragma unroll
        for (int j = 0; j < 4; j++) acc[nt][j] = 0.f;

    for (int k0 = 0; k0 < 128; k0 += 16) {
        __syncthreads();
        stage_A(g_MH, b * NSEQ + r0, k0, t, sAh, sAl);
        stage_A_sum(nodes, graph, b * NSEQ + c0, k0, t, sBh, sBl);
        __syncthreads();
        mma_step(sAh, sAl, sBh, sBl, wid, g, tq, acc);
    }

    const float inv_sqrt_emb = 0.08838834764831845f;  // 1/sqrt(128)
    int r_lo = r0 + wid * 16 + g;
    int r_hi = r_lo + 8;
#pragma unroll
    for (int nt = 0; nt < 16; nt++) {
        int c = c0 + nt * 8 + tq * 2;
        size_t gi0 = (size_t)(b * NSEQ + r_lo) * NSEQ + c;
        size_t gi1 = (size_t)(b * NSEQ + r_hi) * NSEQ + c;
        float2 m0 = *reinterpret_cast<const float2*>(&mask[gi0]);
        float2 m1 = *reinterpret_cast<const float2*>(&mask[gi1]);
        *reinterpret_cast<float2*>(&out[gi0]) = make_float2(
            fmaf(10.f, fast_tanh(acc[nt][0] * inv_sqrt_emb), m0.x),
            fmaf(10.f, fast_tanh(acc[nt][1] * inv_sqrt_emb), m0.y));
        *reinterpret_cast<float2*>(&out[gi1]) = make_float2(
            fmaf(10.f, fast_tanh(acc[nt][2] * inv_sqrt_emb), m1.x),
            fmaf(10.f, fast_tanh(acc[nt][3] * inv_sqrt_emb), m1.y));
    }
}

// ======================================================================
// dual attention via m16n8k16 bf16 MMA with hi/lo split (unchanged).
// grid (4, NHEAD, BATCH), block 256.
// ======================================================================
__global__ void __launch_bounds__(256) attn_kernel(const float* __restrict__ mask) {
    __shared__ uint32_t sKh[32 * 9],  sKl[32 * 9];
    __shared__ uint32_t sKeh[32 * 9], sKel[32 * 9];
    __shared__ __nv_bfloat16 sVh[16 * 40],  sVl[16 * 40];
    __shared__ __nv_bfloat16 sVeh[16 * 40], sVel[16 * 40];

    int t = threadIdx.x;
    int lane = t & 31, wid = t >> 5;
    int g = lane >> 2, tq = lane & 3;
    int b = blockIdx.z, h = blockIdx.y;
    int r0 = blockIdx.x * 128;
    int rw = wid * 16;

    uint32_t qh[4], ql[4];
    {
        const float* qp = g_Q + ((size_t)(b * NSEQ + r0 + rw + g) * EMB + h * HDIM);
        float2 v;
        v = *reinterpret_cast<const float2*>(qp + 2 * tq);                 split2(v.x, v.y, qh[0], ql[0]);
        v = *reinterpret_cast<const float2*>(qp + 8 * EMB + 2 * tq);       split2(v.x, v.y, qh[1], ql[1]);
        v = *reinterpret_cast<const float2*>(qp + 2 * tq + 8);             split2(v.x, v.y, qh[2], ql[2]);
        v = *reinterpret_cast<const float2*>(qp + 8 * EMB + 2 * tq + 8);   split2(v.x, v.y, qh[3], ql[3]);
    }

    float o1[2][4] = {{0,0,0,0},{0,0,0,0}};
    float o2[2][4] = {{0,0,0,0},{0,0,0,0}};
    float la1 = 0.f, lb1 = 0.f, la2 = 0.f, lb2 = 0.f;

    int sidx = t & 127;
    int sm = sidx >> 2, sd4 = (sidx & 3) * 4;
    bool first_half = (t < 128);

    const float* maskrow0 = mask + ((size_t)(b * NSEQ + r0 + rw + g) * NSEQ);
    const float* maskrow1 = maskrow0 + 8 * NSEQ;

    for (int c0 = 0; c0 < NSEQ; c0 += 32) {
        __syncthreads();
        {
            const float* src = first_half ? g_K : g_Ke;
            uint32_t* dh = first_half ? sKh : sKeh;
            uint32_t* dl = first_half ? sKl : sKel;
            float4 v = *reinterpret_cast<const float4*>(
                src + ((size_t)(b * NSEQ + c0 + sm) * EMB + h * HDIM + sd4));
            uint32_t h0, l0, h1, l1;
            split2(v.x, v.y, h0, l0);
            split2(v.z, v.w, h1, l1);
            dh[sm * 9 + sd4 / 2]     = h0;
            dh[sm * 9 + sd4 / 2 + 1] = h1;
            dl[sm * 9 + sd4 / 2]     = l0;
            dl[sm * 9 + sd4 / 2 + 1] = l1;
        }
        {
            const float* src = first_half ? g_V : g_Ve;
            __nv_bfloat16* dh = first_half ? sVh : sVeh;
            __nv_bfloat16* dl = first_half ? sVl : sVel;
            float4 v = *reinterpret_cast<const float4*>(
                src + ((size_t)(b * NSEQ + c0 + sm) * EMB + h * HDIM + sd4));
            float vv[4] = {v.x, v.y, v.z, v.w};
#pragma unroll
            for (int j = 0; j < 4; j++) {
                __nv_bfloat16 hi = __float2bfloat16(vv[j]);
                __nv_bfloat16 lo = __float2bfloat16(vv[j] - __bfloat162float(hi));
                dh[(sd4 + j) * 40 + sm] = hi;
                dl[(sd4 + j) * 40 + sm] = lo;
            }
        }
        __syncthreads();

        float S1[4][4], S2[4][4];
#pragma unroll
        for (int nt = 0; nt < 4; nt++) {
#pragma unroll
            for (int j = 0; j < 4; j++) { S1[nt][j] = 0.f; S2[nt][j] = 0.f; }
            int mrow = nt * 8 + g;
            uint32_t b0h = sKh[mrow * 9 + tq],     b1h = sKh[mrow * 9 + tq + 4];
            uint32_t b0l = sKl[mrow * 9 + tq],     b1l = sKl[mrow * 9 + tq + 4];
            mma_bf16(S1[nt], qh[0], qh[1], qh[2], qh[3], b0h, b1h);
            mma_bf16(S1[nt], qh[0], qh[1], qh[2], qh[3], b0l, b1l);
            mma_bf16(S1[nt], ql[0], ql[1], ql[2], ql[3], b0h, b1h);
            uint32_t e0h = sKeh[mrow * 9 + tq],    e1h = sKeh[mrow * 9 + tq + 4];
            uint32_t e0l = sKel[mrow * 9 + tq],    e1l = sKel[mrow * 9 + tq + 4];
            mma_bf16(S2[nt], qh[0], qh[1], qh[2], qh[3], e0h, e1h);
            mma_bf16(S2[nt], qh[0], qh[1], qh[2], qh[3], e0l, e1l);
            mma_bf16(S2[nt], ql[0], ql[1], ql[2], ql[3], e0h, e1h);
        }

#pragma unroll
        for (int nt = 0; nt < 4; nt++) {
            int cc = c0 + nt * 8 + tq * 2;
            float2 m0 = *reinterpret_cast<const float2*>(maskrow0 + cc);
            float2 m1 = *reinterpret_cast<const float2*>(maskrow1 + cc);
            float p;
            p = __expf(fminf(fmaf(S1[nt][0], 0.25f, m0.x), 60.f)); S1[nt][0] = p; la1 += p;
            p = __expf(fminf(fmaf(S1[nt][1], 0.25f, m0.y), 60.f)); S1[nt][1] = p; la1 += p;
            p = __expf(fminf(fmaf(S1[nt][2], 0.25f, m1.x), 60.f)); S1[nt][2] = p; lb1 += p;
            p = __expf(fminf(fmaf(S1[nt][3], 0.25f, m1.y), 60.f)); S1[nt][3] = p; lb1 += p;
            p = __expf(fminf(fmaf(S2[nt][0], 0.25f, m0.x), 60.f)); S2[nt][0] = p; la2 += p;
            p = __expf(fminf(fmaf(S2[nt][1], 0.25f, m0.y), 60.f)); S2[nt][1] = p; la2 += p;
            p = __expf(fminf(fmaf(S2[nt][2], 0.25f, m1.x), 60.f)); S2[nt][2] = p; lb2 += p;
            p = __expf(fminf(fmaf(S2[nt][3], 0.25f, m1.y), 60.f)); S2[nt][3] = p; lb2 += p;
        }

#pragma unroll
        for (int ks = 0; ks < 2; ks++) {
            uint32_t a1h[4], a1l[4], a2h[4], a2l[4];
            split2(S1[2*ks][0],   S1[2*ks][1],   a1h[0], a1l[0]);
            split2(S1[2*ks][2],   S1[2*ks][3],   a1h[1], a1l[1]);
            split2(S1[2*ks+1][0], S1[2*ks+1][1], a1h[2], a1l[2]);
            split2(S1[2*ks+1][2], S1[2*ks+1][3], a1h[3], a1l[3]);
            split2(S2[2*ks][0],   S2[2*ks][1],   a2h[0], a2l[0]);
            split2(S2[2*ks][2],   S2[2*ks][3],   a2h[1], a2l[1]);
            split2(S2[2*ks+1][0], S2[2*ks+1][1], a2h[2], a2l[2]);
            split2(S2[2*ks+1][2], S2[2*ks+1][3], a2h[3], a2l[3]);
#pragma unroll
            for (int dt = 0; dt < 2; dt++) {
                int d = dt * 8 + g;
                int m0i = (ks * 8 + tq) * 2, m1i = (ks * 8 + 4 + tq) * 2;
                uint32_t vb0h = *reinterpret_cast<uint32_t*>(&sVh[d * 40 + m0i]);
                uint32_t vb1h = *reinterpret_cast<uint32_t*>(&sVh[d * 40 + m1i]);
                uint32_t vb0l = *reinterpret_cast<uint32_t*>(&sVl[d * 40 + m0i]);
                uint32_t vb1l = *reinterpret_cast<uint32_t*>(&sVl[d * 40 + m1i]);
                mma_bf16(o1[dt], a1h[0], a1h[1], a1h[2], a1h[3], vb0h, vb1h);
                mma_bf16(o1[dt], a1h[0], a1h[1], a1h[2], a1h[3], vb0l, vb1l);
                mma_bf16(o1[dt], a1l[0], a1l[1], a1l[2], a1l[3], vb0h, vb1h);
                uint32_t wb0h = *reinterpret_cast<uint32_t*>(&sVeh[d * 40 + m0i]);
                uint32_t wb1h = *reinterpret_cast<uint32_t*>(&sVeh[d * 40 + m1i]);
                uint32_t wb0l = *reinterpret_cast<uint32_t*>(&sVel[d * 40 + m0i]);
                uint32_t wb1l = *reinterpret_cast<uint32_t*>(&sVel[d * 40 + m1i]);
                mma_bf16(o2[dt], a2h[0], a2h[1], a2h[2], a2h[3], wb0h, wb1h);
                mma_bf16(o2[dt], a2h[0], a2h[1], a2h[2], a2h[3], wb0l, wb1l);
                mma_bf16(o2[dt], a2l[0], a2l[1], a2l[2], a2l[3], wb0h, wb1h);
            }
        }
    }

    la1 += __shfl_xor_sync(0xffffffffu, la1, 1); la1 += __shfl_xor_sync(0xffffffffu, la1, 2);
    lb1 += __shfl_xor_sync(0xffffffffu, lb1, 1); lb1 += __shfl_xor_sync(0xffffffffu, lb1, 2);
    la2 += __shfl_xor_sync(0xffffffffu, la2, 1); la2 += __shfl_xor_sync(0xffffffffu, la2, 2);
    lb2 += __shfl_xor_sync(0xffffffffu, lb2, 1); lb2 += __shfl_xor_sync(0xffffffffu, lb2, 2);
    float ia1 = 1.f / la1, ib1 = 1.f / lb1, ia2 = 1.f / la2, ib2 = 1.f / lb2;

    {
        size_t base0 = (size_t)(b * NSEQ + r0 + rw + g) * EMB + h * HDIM;
        size_t base1 = base0 + 8 * EMB;
#pragma unroll
        for (int dt = 0; dt < 2; dt++) {
            int dcol = dt * 8 + tq * 2;
            *reinterpret_cast<float2*>(g_O1 + base0 + dcol) = make_float2(o1[dt][0] * ia1, o1[dt][1] * ia1);
            *reinterpret_cast<float2*>(g_O1 + base1 + dcol) = make_float2(o1[dt][2] * ib1, o1[dt][3] * ib1);
            *reinterpret_cast<float2*>(g_O2 + base0 + dcol) = make_float2(o2[dt][0] * ia2, o2[dt][1] * ia2);
            *reinterpret_cast<float2*>(g_O2 + base1 + dcol) = make_float2(o2[dt][2] * ib2, o2[dt][3] * ib2);
        }
    }
}

// ---------------- in-place row softmax over d_out ----------------
__global__ void softmax_kernel(float* __restrict__ out) {
    float4* p = reinterpret_cast<float4*>(out + (size_t)blockIdx.x * NSEQ);
    int t = threadIdx.x;  // 128 threads
    float4 v = p[t];
    float mx = fmaxf(fmaxf(v.x, v.y), fmaxf(v.z, v.w));
#pragma unroll
    for (int o = 16; o; o >>= 1) mx = fmaxf(mx, __shfl_xor_sync(0xffffffffu, mx, o));
    __shared__ float sm[4];
    if ((t & 31) == 0) sm[t >> 5] = mx;
    __syncthreads();
    mx = fmaxf(fmaxf(sm[0], sm[1]), fmaxf(sm[2], sm[3]));

    v.x = __expf(v.x - mx); v.y = __expf(v.y - mx);
    v.z = __expf(v.z - mx); v.w = __expf(v.w - mx);
    float sum = v.x + v.y + v.z + v.w;
#pragma unroll
    for (int o = 16; o; o >>= 1) sum += __shfl_xor_sync(0xffffffffu, sum, o);
    __shared__ float ss[4];
    if ((t & 31) == 0) ss[t >> 5] = sum;
    __syncthreads();
    sum = ss[0] + ss[1] + ss[2] + ss[3];

    float inv = 1.f / sum;
    v.x *= inv; v.y *= inv; v.z *= inv; v.w *= inv;
    p[t] = v;
}

// ---------------- launch ----------------
extern "C" void kernel_launch(void* const* d_in, const int* in_sizes, int n_in,
                              void* d_out, int out_size) {
    const float* enc_nodes = (const float*)d_in[0];
    const float* enc_graph = (const float*)d_in[1];
    const float* enc_q1    = (const float*)d_in[2];
    const float* enc_fg    = (const float*)d_in[3];
    const float* enc_ln    = (const float*)d_in[4];
    const float* enc_lg    = (const float*)d_in[5];
    const float* mask      = (const float*)d_in[6];
    const float* Wq_first  = (const float*)d_in[7];
    const float* Wq_last   = (const float*)d_in[8];
    const float* Wk        = (const float*)d_in[9];
    const float* Wv        = (const float*)d_in[10];
    const float* Wq_first_e= (const float*)d_in[11];
    const float* Wq_last_e = (const float*)d_in[12];
    const float* Wk_e      = (const float*)d_in[13];
    const float* Wv_e      = (const float*)d_in[14];
    const float* Wcomb1    = (const float*)d_in[15];
    const float* bcomb1    = (const float*)d_in[16];
    const float* Wcomb2    = (const float*)d_in[17];
    const float* bcomb2    = (const float*)d_in[18];
    float* out = (float*)d_out;

    proj4_kernel<<<dim3(128, 4), 256>>>(enc_nodes, enc_graph, Wk, Wv, Wk_e, Wv_e);
    qproj_kernel<<<128, 256>>>(enc_q1, Wq_first, enc_ln, Wq_last,
                               enc_fg, Wq_first_e, enc_lg, Wq_last_e);
    attn_kernel<<<dim3(4, NHEAD, BATCH), 256>>>(mask);
    comb_kernel<<<128, 256>>>(Wcomb1, bcomb1, Wcomb2, bcomb2);
    score_kernel<<<dim3(4, 4, BATCH), 256>>>(enc_nodes, enc_graph, mask, out);
    softmax_kernel<<<BATCH * NSEQ, 128>>>(out);
}